// round 8
// baseline (speedup 1.0000x reference)
#include <cuda_runtime.h>
#include <cuda_bf16.h>
#include <math.h>
#include <stdint.h>
#include <string.h>

// ---------------- problem constants ----------------
#define BN      16384
#define HIDN    512
#define G4      2048
#define HLEN    15
#define DIM     1024

// ---------------- LSTM mma bf16 config ----------------
#define LTPB    256            // 8 warps
#define LM      32             // rows per CTA (halved: 2 CTAs/SM)
#define NCTA    (BN/LM)        // 512 CTAs
#define HSW     260            // h row stride in u32 words (=520 bf16)

// LSTM smem layout (bytes) — total 98,816 -> 2 CTAs/SM
#define OFF_H0   0              // 32*520*2 = 33280
#define OFF_H1   33280
#define OFF_TRJ  66560          // 32*60*4  = 7680
#define OFF_WIH  74240          // 2048*8   = 16384 (bf16x4 per row)
#define OFF_BIAS 90624          // 2048*4   = 8192
#define LSMEM    98816

// fuse_mma smem layout (bytes)
#define FO_HS    0              // 64*260 u32  = 66560
#define FO_HB    66560          // 64*2 f32    = 512
#define FO_RS    67072          // 64*32 f32   = 8192
#define FO_RQ    75264          // 8192
#define FO_MU    83456          // 256
#define FO_RV    83712          // 256
#define FSMEM    83968
#define FM       64             // rows per fuse CTA

// ---------------- device scratch ----------------
__device__ float    g_c  [BN * HIDN];      // LSTM cell state
__device__ float    g_hn [BN * HIDN];      // final hidden (fp32)
__device__ float    g_alpha[32];
__device__ uint32_t g_Wf [G4 * HIDN / 2];  // W_hh bf16x2 fragment order
__device__ uint32_t g_Wrf[DIM * HIDN / 2]; // W_rel bf16x2 fragment order
__device__ uint2    g_wihp[G4];            // permuted W_ih rows (bf16x4)
__device__ float    g_biasp[G4];

// ---------------- helpers ----------------
__device__ __forceinline__ float sigmoid_f(float x){ return 1.0f/(1.0f+__expf(-x)); }
__device__ __forceinline__ float tanh_f(float x){
    float a=fabsf(x), e=__expf(-2.0f*a); return copysignf((1.0f-e)/(1.0f+e), x);
}
#define MMA_BF16(c, a, b0, b1) \
    asm volatile("mma.sync.aligned.m16n8k16.row.col.f32.bf16.bf16.f32 " \
        "{%0,%1,%2,%3}, {%4,%5,%6,%7}, {%8,%9}, {%0,%1,%2,%3};" \
        : "+f"((c)[0]), "+f"((c)[1]), "+f"((c)[2]), "+f"((c)[3]) \
        : "r"((a)[0]), "r"((a)[1]), "r"((a)[2]), "r"((a)[3]), "r"(b0), "r"(b1))

// ---------------------------------------------------------------------------
// reorder: W_hh -> g_Wf (gate-permuted fragment order); W_rel -> g_Wrf.
// blocks 0..2047 : W_hh cols; blocks 2048..3071 : W_rel cols.
// ---------------------------------------------------------------------------
__global__ void reorder_kernel(const float* __restrict__ Whh, const float* __restrict__ Wih,
                               const float* __restrict__ bih, const float* __restrict__ bhh,
                               const float* __restrict__ Wrel)
{
    if (blockIdx.x < G4) {
        int n = blockIdx.x;
        int cw = n & 63, chunk = n >> 6;
        int j = cw >> 3, qq = (cw >> 1) & 3, r = cw & 1;
        int gate, ul;
        if (j < 4) { ul = j*4 + qq;     gate = r;     }
        else       { ul = (j-4)*4 + qq; gate = 2 + r; }
        int srow = gate * HIDN + chunk * 16 + ul;

        const float* src = Whh + (size_t)srow * HIDN;
        int pass = n >> 9, w = (n >> 6) & 7, nt = (n >> 3) & 7, g8 = n & 7;

        for (int k2 = threadIdx.x; k2 < HIDN/2; k2 += blockDim.x) {
            int k = k2 * 2;
            int ksl = k >> 4, kin = k & 15;
            int jj = kin >> 3, qk = (kin >> 1) & 3;
            __nv_bfloat162 p = __floats2bfloat162_rn(src[k], src[k+1]);
            uint32_t u; memcpy(&u, &p, 4);
            int lane = g8*4 + qk;
            size_t idx = ((((((size_t)pass*32 + ksl)*8 + w)*8 + nt)*32 + lane)*2 + jj);
            g_Wf[idx] = u;
        }
        if (threadIdx.x == 0) {
            float4 wv = ((const float4*)Wih)[srow];
            __nv_bfloat162 p0 = __floats2bfloat162_rn(wv.x, wv.y);
            __nv_bfloat162 p1 = __floats2bfloat162_rn(wv.z, wv.w);
            uint2 u; memcpy(&u.x, &p0, 4); memcpy(&u.y, &p1, 4);
            g_wihp[n]  = u;
            g_biasp[n] = bih[srow] + bhh[srow];
        }
    } else {
        int n = blockIdx.x - G4;            // output col 0..1023
        const float* src = Wrel + (size_t)n * HIDN;
        int w = n >> 7, ch = (n >> 6) & 1, nt = (n >> 3) & 7, g8 = n & 7;
        for (int k2 = threadIdx.x; k2 < HIDN/2; k2 += blockDim.x) {
            int k = k2 * 2;
            int ksl = k >> 4, kin = k & 15;
            int jj = kin >> 3, qk = (kin >> 1) & 3;
            __nv_bfloat162 p = __floats2bfloat162_rn(src[k], src[k+1]);
            uint32_t u; memcpy(&u, &p, 4);
            int lane = g8*4 + qk;
            size_t idx = ((((((size_t)(w*2 + ch))*32 + ksl)*8 + nt)*32 + lane)*2 + jj);
            g_Wrf[idx] = u;
        }
    }
}

// ---------------------------------------------------------------------------
// LSTM via mma.sync bf16. 512 CTAs x 256 threads, 2 CTAs/SM; 32 rows each.
// B streamed from L2 in fragment order; h double-buffered bf16 in smem;
// one barrier per timestep. Epilogue of one CTA overlaps MMA of the other.
// ---------------------------------------------------------------------------
__global__ __launch_bounds__(LTPB, 2)
void lstm_mma_kernel(const float* __restrict__ traj)
{
    extern __shared__ char smem[];
    float* trj    = (float*)(smem + OFF_TRJ);     // [32][60]
    uint2* wih_s  = (uint2*)(smem + OFF_WIH);     // [2048] bf16x4
    float* bias_s = (float*)(smem + OFF_BIAS);    // [2048]

    const int tid = threadIdx.x;
    const int lane = tid & 31, warpid = tid >> 5;
    const int q = lane & 3, g8 = lane >> 2;
    const int m0 = blockIdx.x * LM;

    for (int i = tid; i < (LM*HLEN*4)/4; i += LTPB)
        ((float4*)trj)[i] = ((const float4*)(traj + (size_t)m0 * (HLEN*4)))[i];
    for (int i = tid; i < G4; i += LTPB) {
        wih_s[i]  = g_wihp[i];
        bias_s[i] = g_biasp[i];
    }
    __syncthreads();

    const uint2* __restrict__ Wf64 = (const uint2*)g_Wf;

    for (int t = 0; t < HLEN; ++t) {
        const uint32_t* hcur = (const uint32_t*)(smem + ((t & 1) ? OFF_H1 : OFF_H0));
        __nv_bfloat16*  hnxt = (__nv_bfloat16*)(smem + ((t & 1) ? OFF_H0 : OFF_H1));

        for (int ncp = 0; ncp < 4; ++ncp) {
            float acc[2][8][4];
            #pragma unroll
            for (int mt = 0; mt < 2; ++mt)
                #pragma unroll
                for (int nt = 0; nt < 8; ++nt)
                    #pragma unroll
                    for (int c = 0; c < 4; ++c) acc[mt][nt][c] = 0.0f;

            if (t > 0) {
                const uint2* Bp = Wf64 + ((((size_t)ncp*32)*8 + warpid)*8)*32 + lane;
                uint2 bc[8], bn[8];
                #pragma unroll
                for (int nt = 0; nt < 8; ++nt) bc[nt] = Bp[nt*32];

                for (int ksl = 0; ksl < 32; ++ksl) {
                    if (ksl < 31) {
                        const uint2* Bn = Bp + (size_t)(ksl + 1) * 2048;
                        #pragma unroll
                        for (int nt = 0; nt < 8; ++nt) bn[nt] = Bn[nt*32];
                    }
                    uint32_t a[2][4];
                    const int kw = ksl * 8 + q;
                    #pragma unroll
                    for (int mt = 0; mt < 2; ++mt) {
                        int r0 = (mt*16 + g8) * HSW + kw;
                        a[mt][0] = hcur[r0];
                        a[mt][1] = hcur[r0 + 8*HSW];
                        a[mt][2] = hcur[r0 + 4];
                        a[mt][3] = hcur[r0 + 8*HSW + 4];
                    }
                    #pragma unroll
                    for (int nt = 0; nt < 8; ++nt) {
                        #pragma unroll
                        for (int mt = 0; mt < 2; ++mt)
                            MMA_BF16(acc[mt][nt], a[mt], bc[nt].x, bc[nt].y);
                    }
                    #pragma unroll
                    for (int nt = 0; nt < 8; ++nt) bc[nt] = bn[nt];
                }
            }

            // ---- epilogue: pass covers hidden units [ncp*128, ncp*128+128) ----
            #pragma unroll
            for (int mt = 0; mt < 2; ++mt) {
                #pragma unroll
                for (int half = 0; half < 2; ++half) {
                    const int row = mt*16 + g8 + half*8;
                    const int gr  = m0 + row;
                    const float4 xv = *(const float4*)(trj + row*60 + t*4);
                    #pragma unroll
                    for (int j = 0; j < 4; ++j) {
                        const int pi = ncp*512 + warpid*64 + j*8 + q*2;
                        const int pg = pi + 32;
                        uint2 ui = wih_s[pi],   uf = wih_s[pi+1];
                        uint2 ug = wih_s[pg],   uo = wih_s[pg+1];
                        float2 wi0 = __bfloat1622float2(*(__nv_bfloat162*)&ui.x);
                        float2 wi1 = __bfloat1622float2(*(__nv_bfloat162*)&ui.y);
                        float2 wf0 = __bfloat1622float2(*(__nv_bfloat162*)&uf.x);
                        float2 wf1 = __bfloat1622float2(*(__nv_bfloat162*)&uf.y);
                        float2 wg0 = __bfloat1622float2(*(__nv_bfloat162*)&ug.x);
                        float2 wg1 = __bfloat1622float2(*(__nv_bfloat162*)&ug.y);
                        float2 wo0 = __bfloat1622float2(*(__nv_bfloat162*)&uo.x);
                        float2 wo1 = __bfloat1622float2(*(__nv_bfloat162*)&uo.y);
                        float gi = acc[mt][j  ][half*2  ] + bias_s[pi  ] + xv.x*wi0.x + xv.y*wi0.y + xv.z*wi1.x + xv.w*wi1.y;
                        float gf = acc[mt][j  ][half*2+1] + bias_s[pi+1] + xv.x*wf0.x + xv.y*wf0.y + xv.z*wf1.x + xv.w*wf1.y;
                        float gg = acc[mt][j+4][half*2  ] + bias_s[pg  ] + xv.x*wg0.x + xv.y*wg0.y + xv.z*wg1.x + xv.w*wg1.y;
                        float go = acc[mt][j+4][half*2+1] + bias_s[pg+1] + xv.x*wo0.x + xv.y*wo0.y + xv.z*wo1.x + xv.w*wo1.y;
                        const int kg = ncp*128 + warpid*16 + j*4 + q;
                        const size_t idx = (size_t)gr * HIDN + kg;
                        float cp = (t > 0) ? g_c[idx] : 0.0f;
                        float cn = sigmoid_f(gf) * cp + sigmoid_f(gi) * tanh_f(gg);
                        g_c[idx] = cn;
                        float hn = sigmoid_f(go) * tanh_f(cn);
                        hnxt[row*520 + kg] = __float2bfloat16_rn(hn);
                        if (t == HLEN - 1) g_hn[idx] = hn;
                    }
                }
            }
        }
        __syncthreads();
    }
}

// ---------------------------------------------------------------------------
__global__ void alpha_kernel(const float* __restrict__ ego_speed, const float* __restrict__ gps_conf,
                             const float* __restrict__ W_g1, const float* __restrict__ b_g1,
                             const float* __restrict__ W_g2, const float* __restrict__ b_g2)
{
    int b = threadIdx.x;
    if (b < 32) {
        float s = ego_speed[b], c = gps_conf[b];
        float acc = b_g2[0];
        #pragma unroll
        for (int h = 0; h < 16; ++h) {
            float t = W_g1[2*h]*s + W_g1[2*h+1]*c + b_g1[h];
            acc += W_g2[h] * fmaxf(t, 0.0f);
        }
        g_alpha[b] = 1.0f / (1.0f + expf(-acc));
    }
}

// ---------------------------------------------------------------------------
// fuse via mma.sync bf16 (unchanged from R7 — proven at 132 us)
// ---------------------------------------------------------------------------
__global__ __launch_bounds__(LTPB, 1)
void fuse_mma_kernel(const float* __restrict__ tokens, const float* __restrict__ habs,
                     const float* __restrict__ W_abs,
                     const float* __restrict__ gamma, const float* __restrict__ beta,
                     float* __restrict__ out)
{
    extern __shared__ char smem[];
    uint32_t* hs   = (uint32_t*)(smem + FO_HS);
    float*    hb   = (float*)   (smem + FO_HB);
    float*    redS = (float*)   (smem + FO_RS);
    float*    redQ = (float*)   (smem + FO_RQ);
    float*    mu_s = (float*)   (smem + FO_MU);
    float*    rs_s = (float*)   (smem + FO_RV);

    const int tid = threadIdx.x;
    const int lane = tid & 31, warpid = tid >> 5;
    const int q = lane & 3, g8 = lane >> 2;
    const int m0 = blockIdx.x * FM;

    for (int i = tid; i < FM*256; i += LTPB) {
        int row = i >> 8, kw = i & 255;
        float2 v = ((const float2*)(g_hn + (size_t)(m0 + row)*HIDN))[kw];
        __nv_bfloat162 p = __floats2bfloat162_rn(v.x, v.y);
        uint32_t u; memcpy(&u, &p, 4);
        hs[row*HSW + kw] = u;
    }
    for (int i = tid; i < FM*2; i += LTPB) hb[i] = habs[(size_t)m0*2 + i];
    __syncthreads();

    const float al = g_alpha[m0 >> 9], ali = 1.0f - al;
    const uint2* __restrict__ Wr64 = (const uint2*)g_Wrf;

    float rsum[8], rq[8];
    #pragma unroll
    for (int s = 0; s < 8; ++s) { rsum[s] = 0.0f; rq[s] = 0.0f; }

    #pragma unroll
    for (int ch = 0; ch < 2; ++ch) {
        float acc[4][8][4];
        #pragma unroll
        for (int mt = 0; mt < 4; ++mt)
            #pragma unroll
            for (int nt = 0; nt < 8; ++nt)
                #pragma unroll
                for (int c = 0; c < 4; ++c) acc[mt][nt][c] = 0.0f;

        const uint2* Bp = Wr64 + ((size_t)(warpid*2 + ch)*32*8)*32 + lane;
        uint2 bc[8], bn[8];
        #pragma unroll
        for (int nt = 0; nt < 8; ++nt) bc[nt] = Bp[nt*32];

        for (int ksl = 0; ksl < 32; ++ksl) {
            if (ksl < 31) {
                const uint2* Bn = Bp + (size_t)(ksl + 1) * 256;
                #pragma unroll
                for (int nt = 0; nt < 8; ++nt) bn[nt] = Bn[nt*32];
            }
            uint32_t a[4][4];
            const int kw = ksl * 8 + q;
            #pragma unroll
            for (int mt = 0; mt < 4; ++mt) {
                int r0 = (mt*16 + g8) * HSW + kw;
                a[mt][0] = hs[r0];
                a[mt][1] = hs[r0 + 8*HSW];
                a[mt][2] = hs[r0 + 4];
                a[mt][3] = hs[r0 + 8*HSW + 4];
            }
            #pragma unroll
            for (int nt = 0; nt < 8; ++nt) {
                #pragma unroll
                for (int mt = 0; mt < 4; ++mt)
                    MMA_BF16(acc[mt][nt], a[mt], bc[nt].x, bc[nt].y);
            }
            #pragma unroll
            for (int nt = 0; nt < 8; ++nt) bc[nt] = bn[nt];
        }

        #pragma unroll
        for (int mt = 0; mt < 4; ++mt) {
            #pragma unroll
            for (int half = 0; half < 2; ++half) {
                const int row = mt*16 + g8 + half*8;
                const int R   = m0 + row;
                const float h0 = hb[row*2], h1 = hb[row*2+1];
                const int slot = mt*2 + half;
                #pragma unroll
                for (int nt = 0; nt < 8; ++nt) {
                    const int col = warpid*128 + ch*64 + nt*8 + q*2;
                    float2 tk  = *(const float2*)(tokens + (size_t)R*DIM + col);
                    float2 wa0 = ((const float2*)W_abs)[col];
                    float2 wa1 = ((const float2*)W_abs)[col+1];
                    float x0 = tk.x + al*acc[mt][nt][half*2  ] + ali*(h0*wa0.x + h1*wa0.y);
                    float x1 = tk.y + al*acc[mt][nt][half*2+1] + ali*(h0*wa1.x + h1*wa1.y);
                    *(float2*)(out + (size_t)R*DIM + col) = make_float2(x0, x1);
                    rsum[slot] += x0 + x1;
                    rq[slot]   += x0*x0 + x1*x1;
                }
            }
        }
    }

    __syncthreads();
    #pragma unroll
    for (int mt = 0; mt < 4; ++mt)
        #pragma unroll
        for (int half = 0; half < 2; ++half) {
            const int row = mt*16 + g8 + half*8;
            redS[row*32 + warpid*4 + q] = rsum[mt*2 + half];
            redQ[row*32 + warpid*4 + q] = rq[mt*2 + half];
        }
    __syncthreads();
    if (tid < FM) {
        float s = 0.0f, qq = 0.0f;
        #pragma unroll
        for (int i = 0; i < 32; ++i) { s += redS[tid*32 + i]; qq += redQ[tid*32 + i]; }
        float mu = s * (1.0f/DIM);
        float var = qq * (1.0f/DIM) - mu*mu;
        mu_s[tid] = mu; rs_s[tid] = rsqrtf(var + 1e-5f);
    }
    __syncthreads();

    for (int i = tid; i < (FM*DIM)/4; i += LTPB) {
        int mm = i >> 8, j4 = i & 255;
        float4 v = ((float4*)(out + (size_t)(m0 + mm)*DIM))[j4];
        float4 g = ((const float4*)gamma)[j4];
        float4 b = ((const float4*)beta)[j4];
        float mu = mu_s[mm], rr = rs_s[mm];
        v.x = (v.x - mu)*rr*g.x + b.x;
        v.y = (v.y - mu)*rr*g.y + b.y;
        v.z = (v.z - mu)*rr*g.z + b.z;
        v.w = (v.w - mu)*rr*g.w + b.w;
        ((float4*)(out + (size_t)(m0 + mm)*DIM))[j4] = v;
    }
}

// ---------------------------------------------------------------------------
extern "C" void kernel_launch(void* const* d_in, const int* in_sizes, int n_in,
                              void* d_out, int out_size)
{
    const float* tokens = (const float*)d_in[0];
    const float* traj   = (const float*)d_in[1];
    const float* habs   = (const float*)d_in[2];
    const float* espeed = (const float*)d_in[3];
    const float* gconf  = (const float*)d_in[4];
    const float* W_ih   = (const float*)d_in[5];
    const float* W_hh   = (const float*)d_in[6];
    const float* b_ih   = (const float*)d_in[7];
    const float* b_hh   = (const float*)d_in[8];
    const float* W_rel  = (const float*)d_in[9];
    const float* W_abs  = (const float*)d_in[10];
    const float* W_g1   = (const float*)d_in[11];
    const float* b_g1   = (const float*)d_in[12];
    const float* W_g2   = (const float*)d_in[13];
    const float* b_g2   = (const float*)d_in[14];
    const float* gamma  = (const float*)d_in[15];
    const float* beta   = (const float*)d_in[16];
    float* out = (float*)d_out;

    cudaFuncSetAttribute(lstm_mma_kernel, cudaFuncAttributeMaxDynamicSharedMemorySize, LSMEM);
    cudaFuncSetAttribute(fuse_mma_kernel, cudaFuncAttributeMaxDynamicSharedMemorySize, FSMEM);

    reorder_kernel<<<G4 + DIM, 128>>>(W_hh, W_ih, b_ih, b_hh, W_rel);
    lstm_mma_kernel<<<NCTA, LTPB, LSMEM>>>(traj);
    alpha_kernel<<<1, 32>>>(espeed, gconf, W_g1, b_g1, W_g2, b_g2);
    fuse_mma_kernel<<<BN/FM, LTPB, FSMEM>>>(tokens, habs, W_abs, gamma, beta, out);
}

// round 9
// speedup vs baseline: 1.7916x; 1.7916x over previous
#include <cuda_runtime.h>
#include <cuda_bf16.h>
#include <math.h>
#include <stdint.h>
#include <string.h>

// ---------------- problem constants ----------------
#define BN      16384
#define HIDN    512
#define G4      2048
#define HLEN    15
#define DIM     1024

// ---------------- LSTM mma bf16 config (R7 proven) ----------------
#define LTPB    256            // 8 warps
#define LM      64             // rows per CTA
#define NCTA    (BN/LM)        // 256 CTAs
#define HSW     260            // h row stride in u32 words (=520 bf16)

// LSTM smem layout (bytes)
#define OFF_H0   0
#define OFF_H1   66560
#define OFF_TRJ  133120
#define OFF_WIH  148480
#define OFF_BIAS 181248
#define LSMEM    189440

// fuse_mma smem layout (bytes)
#define FO_HS    0              // 64*260 u32  = 66560
#define FO_HB    66560          // 64*2 f32    = 512
#define FO_RS    67072          // 64*32 f32   = 8192
#define FO_RQ    75264          // 8192
#define FO_MU    83456          // 256
#define FO_RV    83712          // 256
#define FSMEM    83968
#define FM       64             // rows per fuse CTA

// ---------------- device scratch ----------------
__device__ float    g_c  [BN * HIDN];      // LSTM cell state
__device__ float    g_hn [BN * HIDN];      // final hidden (fp32)
__device__ float    g_alpha[32];
__device__ uint32_t g_Wf [G4 * HIDN / 2];  // W_hh bf16x2 fragment order
__device__ uint32_t g_Wrf[DIM * HIDN / 2]; // W_rel bf16x2 fragment order
__device__ float4   g_wihp[G4];            // permuted W_ih rows (fp32)
__device__ float    g_biasp[G4];

// ---------------- helpers ----------------
__device__ __forceinline__ float tanh_ap(float x){
    float y; asm("tanh.approx.f32 %0, %1;" : "=f"(y) : "f"(x)); return y;
}
__device__ __forceinline__ float sig_ap(float x){
    return fmaf(tanh_ap(0.5f*x), 0.5f, 0.5f);
}
#define MMA_BF16(c, a, b0, b1) \
    asm volatile("mma.sync.aligned.m16n8k16.row.col.f32.bf16.bf16.f32 " \
        "{%0,%1,%2,%3}, {%4,%5,%6,%7}, {%8,%9}, {%0,%1,%2,%3};" \
        : "+f"((c)[0]), "+f"((c)[1]), "+f"((c)[2]), "+f"((c)[3]) \
        : "r"((a)[0]), "r"((a)[1]), "r"((a)[2]), "r"((a)[3]), "r"(b0), "r"(b1))

// ---------------------------------------------------------------------------
// reorder: W_hh -> g_Wf (gate-permuted fragment order); W_rel -> g_Wrf.
// blocks 0..2047 : W_hh cols; blocks 2048..3071 : W_rel cols.
// ---------------------------------------------------------------------------
__global__ void reorder_kernel(const float* __restrict__ Whh, const float* __restrict__ Wih,
                               const float* __restrict__ bih, const float* __restrict__ bhh,
                               const float* __restrict__ Wrel)
{
    if (blockIdx.x < G4) {
        int n = blockIdx.x;
        int cw = n & 63, chunk = n >> 6;
        int j = cw >> 3, qq = (cw >> 1) & 3, r = cw & 1;
        int gate, ul;
        if (j < 4) { ul = j*4 + qq;     gate = r;     }
        else       { ul = (j-4)*4 + qq; gate = 2 + r; }
        int srow = gate * HIDN + chunk * 16 + ul;

        const float* src = Whh + (size_t)srow * HIDN;
        int pass = n >> 9, w = (n >> 6) & 7, nt = (n >> 3) & 7, g8 = n & 7;

        for (int k2 = threadIdx.x; k2 < HIDN/2; k2 += blockDim.x) {
            int k = k2 * 2;
            int ksl = k >> 4, kin = k & 15;
            int jj = kin >> 3, qk = (kin >> 1) & 3;
            __nv_bfloat162 p = __floats2bfloat162_rn(src[k], src[k+1]);
            uint32_t u; memcpy(&u, &p, 4);
            int lane = g8*4 + qk;
            size_t idx = ((((((size_t)pass*32 + ksl)*8 + w)*8 + nt)*32 + lane)*2 + jj);
            g_Wf[idx] = u;
        }
        if (threadIdx.x == 0) {
            g_wihp[n]  = ((const float4*)Wih)[srow];
            g_biasp[n] = bih[srow] + bhh[srow];
        }
    } else {
        int n = blockIdx.x - G4;            // output col 0..1023
        const float* src = Wrel + (size_t)n * HIDN;
        int w = n >> 7, ch = (n >> 6) & 1, nt = (n >> 3) & 7, g8 = n & 7;
        for (int k2 = threadIdx.x; k2 < HIDN/2; k2 += blockDim.x) {
            int k = k2 * 2;
            int ksl = k >> 4, kin = k & 15;
            int jj = kin >> 3, qk = (kin >> 1) & 3;
            __nv_bfloat162 p = __floats2bfloat162_rn(src[k], src[k+1]);
            uint32_t u; memcpy(&u, &p, 4);
            int lane = g8*4 + qk;
            size_t idx = ((((((size_t)(w*2 + ch))*32 + ksl)*8 + nt)*32 + lane)*2 + jj);
            g_Wrf[idx] = u;
        }
    }
}

// ---------------------------------------------------------------------------
// LSTM via mma.sync bf16. 256 CTAs x 256 threads; 64 rows each (R7 config).
// B streamed from L2 in fragment order; h double-buffered bf16 in smem;
// one barrier per timestep. New: tanh.approx activations + hoisted W_ih loads.
// ---------------------------------------------------------------------------
__global__ __launch_bounds__(LTPB, 1)
void lstm_mma_kernel(const float* __restrict__ traj)
{
    extern __shared__ char smem[];
    float*  trj    = (float*) (smem + OFF_TRJ);   // [64][60]
    float4* wih_s  = (float4*)(smem + OFF_WIH);   // [2048]
    float*  bias_s = (float*) (smem + OFF_BIAS);  // [2048]

    const int tid = threadIdx.x;
    const int lane = tid & 31, warpid = tid >> 5;
    const int q = lane & 3, g8 = lane >> 2;
    const int m0 = blockIdx.x * LM;

    for (int i = tid; i < (LM*HLEN*4)/4; i += LTPB)
        ((float4*)trj)[i] = ((const float4*)(traj + (size_t)m0 * (HLEN*4)))[i];
    for (int i = tid; i < G4; i += LTPB) {
        wih_s[i]  = g_wihp[i];
        bias_s[i] = g_biasp[i];
    }
    __syncthreads();

    const uint2* __restrict__ Wf64 = (const uint2*)g_Wf;

    for (int t = 0; t < HLEN; ++t) {
        const uint32_t* hcur = (const uint32_t*)(smem + ((t & 1) ? OFF_H1 : OFF_H0));
        __nv_bfloat16*  hnxt = (__nv_bfloat16*)(smem + ((t & 1) ? OFF_H0 : OFF_H1));

        for (int ncp = 0; ncp < 4; ++ncp) {
            float acc[4][8][4];
            #pragma unroll
            for (int mt = 0; mt < 4; ++mt)
                #pragma unroll
                for (int nt = 0; nt < 8; ++nt)
                    #pragma unroll
                    for (int c = 0; c < 4; ++c) acc[mt][nt][c] = 0.0f;

            if (t > 0) {
                const uint2* Bp = Wf64 + ((((size_t)ncp*32)*8 + warpid)*8)*32 + lane;
                uint2 bc[8], bn[8];
                #pragma unroll
                for (int nt = 0; nt < 8; ++nt) bc[nt] = Bp[nt*32];

                for (int ksl = 0; ksl < 32; ++ksl) {
                    if (ksl < 31) {
                        const uint2* Bn = Bp + (size_t)(ksl + 1) * 2048;
                        #pragma unroll
                        for (int nt = 0; nt < 8; ++nt) bn[nt] = Bn[nt*32];
                    }
                    uint32_t a[4][4];
                    const int kw = ksl * 8 + q;
                    #pragma unroll
                    for (int mt = 0; mt < 4; ++mt) {
                        int r0 = (mt*16 + g8) * HSW + kw;
                        a[mt][0] = hcur[r0];
                        a[mt][1] = hcur[r0 + 8*HSW];
                        a[mt][2] = hcur[r0 + 4];
                        a[mt][3] = hcur[r0 + 8*HSW + 4];
                    }
                    #pragma unroll
                    for (int nt = 0; nt < 8; ++nt) {
                        #pragma unroll
                        for (int mt = 0; mt < 4; ++mt)
                            MMA_BF16(acc[mt][nt], a[mt], bc[nt].x, bc[nt].y);
                    }
                    #pragma unroll
                    for (int nt = 0; nt < 8; ++nt) bc[nt] = bn[nt];
                }
            }

            // ---- epilogue: pass covers hidden units [ncp*128, ncp*128+128) ----
            // j outer: load the 4 gate weight rows/biases ONCE, sweep 8 rows.
            #pragma unroll
            for (int j = 0; j < 4; ++j) {
                const int pi = ncp*512 + warpid*64 + j*8 + q*2;
                const int pg = pi + 32;
                const float4 wi = wih_s[pi], wf = wih_s[pi+1];
                const float4 wg = wih_s[pg], wo = wih_s[pg+1];
                const float  bi = bias_s[pi],  bf = bias_s[pi+1];
                const float  bg = bias_s[pg],  bo = bias_s[pg+1];
                const int kg = ncp*128 + warpid*16 + j*4 + q;

                #pragma unroll
                for (int mt = 0; mt < 4; ++mt) {
                    #pragma unroll
                    for (int half = 0; half < 2; ++half) {
                        const int row = mt*16 + g8 + half*8;
                        const int gr  = m0 + row;
                        const float4 xv = *(const float4*)(trj + row*60 + t*4);
                        float gi = acc[mt][j  ][half*2  ] + bi + xv.x*wi.x + xv.y*wi.y + xv.z*wi.z + xv.w*wi.w;
                        float gf = acc[mt][j  ][half*2+1] + bf + xv.x*wf.x + xv.y*wf.y + xv.z*wf.z + xv.w*wf.w;
                        float gg = acc[mt][j+4][half*2  ] + bg + xv.x*wg.x + xv.y*wg.y + xv.z*wg.z + xv.w*wg.w;
                        float go = acc[mt][j+4][half*2+1] + bo + xv.x*wo.x + xv.y*wo.y + xv.z*wo.z + xv.w*wo.w;
                        const size_t idx = (size_t)gr * HIDN + kg;
                        float cp = (t > 0) ? g_c[idx] : 0.0f;
                        float cn = sig_ap(gf) * cp + sig_ap(gi) * tanh_ap(gg);
                        g_c[idx] = cn;
                        float hn = sig_ap(go) * tanh_ap(cn);
                        hnxt[row*520 + kg] = __float2bfloat16_rn(hn);
                        if (t == HLEN - 1) g_hn[idx] = hn;
                    }
                }
            }
        }
        __syncthreads();
    }
}

// ---------------------------------------------------------------------------
__global__ void alpha_kernel(const float* __restrict__ ego_speed, const float* __restrict__ gps_conf,
                             const float* __restrict__ W_g1, const float* __restrict__ b_g1,
                             const float* __restrict__ W_g2, const float* __restrict__ b_g2)
{
    int b = threadIdx.x;
    if (b < 32) {
        float s = ego_speed[b], c = gps_conf[b];
        float acc = b_g2[0];
        #pragma unroll
        for (int h = 0; h < 16; ++h) {
            float t = W_g1[2*h]*s + W_g1[2*h+1]*c + b_g1[h];
            acc += W_g2[h] * fmaxf(t, 0.0f);
        }
        g_alpha[b] = 1.0f / (1.0f + expf(-acc));
    }
}

// ---------------------------------------------------------------------------
// fuse via mma.sync bf16 (unchanged from R7 — proven at 132 us)
// ---------------------------------------------------------------------------
__global__ __launch_bounds__(LTPB, 1)
void fuse_mma_kernel(const float* __restrict__ tokens, const float* __restrict__ habs,
                     const float* __restrict__ W_abs,
                     const float* __restrict__ gamma, const float* __restrict__ beta,
                     float* __restrict__ out)
{
    extern __shared__ char smem[];
    uint32_t* hs   = (uint32_t*)(smem + FO_HS);
    float*    hb   = (float*)   (smem + FO_HB);
    float*    redS = (float*)   (smem + FO_RS);
    float*    redQ = (float*)   (smem + FO_RQ);
    float*    mu_s = (float*)   (smem + FO_MU);
    float*    rs_s = (float*)   (smem + FO_RV);

    const int tid = threadIdx.x;
    const int lane = tid & 31, warpid = tid >> 5;
    const int q = lane & 3, g8 = lane >> 2;
    const int m0 = blockIdx.x * FM;

    for (int i = tid; i < FM*256; i += LTPB) {
        int row = i >> 8, kw = i & 255;
        float2 v = ((const float2*)(g_hn + (size_t)(m0 + row)*HIDN))[kw];
        __nv_bfloat162 p = __floats2bfloat162_rn(v.x, v.y);
        uint32_t u; memcpy(&u, &p, 4);
        hs[row*HSW + kw] = u;
    }
    for (int i = tid; i < FM*2; i += LTPB) hb[i] = habs[(size_t)m0*2 + i];
    __syncthreads();

    const float al = g_alpha[m0 >> 9], ali = 1.0f - al;
    const uint2* __restrict__ Wr64 = (const uint2*)g_Wrf;

    float rsum[8], rq[8];
    #pragma unroll
    for (int s = 0; s < 8; ++s) { rsum[s] = 0.0f; rq[s] = 0.0f; }

    #pragma unroll
    for (int ch = 0; ch < 2; ++ch) {
        float acc[4][8][4];
        #pragma unroll
        for (int mt = 0; mt < 4; ++mt)
            #pragma unroll
            for (int nt = 0; nt < 8; ++nt)
                #pragma unroll
                for (int c = 0; c < 4; ++c) acc[mt][nt][c] = 0.0f;

        const uint2* Bp = Wr64 + ((size_t)(warpid*2 + ch)*32*8)*32 + lane;
        uint2 bc[8], bn[8];
        #pragma unroll
        for (int nt = 0; nt < 8; ++nt) bc[nt] = Bp[nt*32];

        for (int ksl = 0; ksl < 32; ++ksl) {
            if (ksl < 31) {
                const uint2* Bn = Bp + (size_t)(ksl + 1) * 256;
                #pragma unroll
                for (int nt = 0; nt < 8; ++nt) bn[nt] = Bn[nt*32];
            }
            uint32_t a[4][4];
            const int kw = ksl * 8 + q;
            #pragma unroll
            for (int mt = 0; mt < 4; ++mt) {
                int r0 = (mt*16 + g8) * HSW + kw;
                a[mt][0] = hs[r0];
                a[mt][1] = hs[r0 + 8*HSW];
                a[mt][2] = hs[r0 + 4];
                a[mt][3] = hs[r0 + 8*HSW + 4];
            }
            #pragma unroll
            for (int nt = 0; nt < 8; ++nt) {
                #pragma unroll
                for (int mt = 0; mt < 4; ++mt)
                    MMA_BF16(acc[mt][nt], a[mt], bc[nt].x, bc[nt].y);
            }
            #pragma unroll
            for (int nt = 0; nt < 8; ++nt) bc[nt] = bn[nt];
        }

        #pragma unroll
        for (int mt = 0; mt < 4; ++mt) {
            #pragma unroll
            for (int half = 0; half < 2; ++half) {
                const int row = mt*16 + g8 + half*8;
                const int R   = m0 + row;
                const float h0 = hb[row*2], h1 = hb[row*2+1];
                const int slot = mt*2 + half;
                #pragma unroll
                for (int nt = 0; nt < 8; ++nt) {
                    const int col = warpid*128 + ch*64 + nt*8 + q*2;
                    float2 tk  = *(const float2*)(tokens + (size_t)R*DIM + col);
                    float2 wa0 = ((const float2*)W_abs)[col];
                    float2 wa1 = ((const float2*)W_abs)[col+1];
                    float x0 = tk.x + al*acc[mt][nt][half*2  ] + ali*(h0*wa0.x + h1*wa0.y);
                    float x1 = tk.y + al*acc[mt][nt][half*2+1] + ali*(h0*wa1.x + h1*wa1.y);
                    *(float2*)(out + (size_t)R*DIM + col) = make_float2(x0, x1);
                    rsum[slot] += x0 + x1;
                    rq[slot]   += x0*x0 + x1*x1;
                }
            }
        }
    }

    __syncthreads();
    #pragma unroll
    for (int mt = 0; mt < 4; ++mt)
        #pragma unroll
        for (int half = 0; half < 2; ++half) {
            const int row = mt*16 + g8 + half*8;
            redS[row*32 + warpid*4 + q] = rsum[mt*2 + half];
            redQ[row*32 + warpid*4 + q] = rq[mt*2 + half];
        }
    __syncthreads();
    if (tid < FM) {
        float s = 0.0f, qq = 0.0f;
        #pragma unroll
        for (int i = 0; i < 32; ++i) { s += redS[tid*32 + i]; qq += redQ[tid*32 + i]; }
        float mu = s * (1.0f/DIM);
        float var = qq * (1.0f/DIM) - mu*mu;
        mu_s[tid] = mu; rs_s[tid] = rsqrtf(var + 1e-5f);
    }
    __syncthreads();

    for (int i = tid; i < (FM*DIM)/4; i += LTPB) {
        int mm = i >> 8, j4 = i & 255;
        float4 v = ((float4*)(out + (size_t)(m0 + mm)*DIM))[j4];
        float4 g = ((const float4*)gamma)[j4];
        float4 b = ((const float4*)beta)[j4];
        float mu = mu_s[mm], rr = rs_s[mm];
        v.x = (v.x - mu)*rr*g.x + b.x;
        v.y = (v.y - mu)*rr*g.y + b.y;
        v.z = (v.z - mu)*rr*g.z + b.z;
        v.w = (v.w - mu)*rr*g.w + b.w;
        ((float4*)(out + (size_t)(m0 + mm)*DIM))[j4] = v;
    }
}

// ---------------------------------------------------------------------------
extern "C" void kernel_launch(void* const* d_in, const int* in_sizes, int n_in,
                              void* d_out, int out_size)
{
    const float* tokens = (const float*)d_in[0];
    const float* traj   = (const float*)d_in[1];
    const float* habs   = (const float*)d_in[2];
    const float* espeed = (const float*)d_in[3];
    const float* gconf  = (const float*)d_in[4];
    const float* W_ih   = (const float*)d_in[5];
    const float* W_hh   = (const float*)d_in[6];
    const float* b_ih   = (const float*)d_in[7];
    const float* b_hh   = (const float*)d_in[8];
    const float* W_rel  = (const float*)d_in[9];
    const float* W_abs  = (const float*)d_in[10];
    const float* W_g1   = (const float*)d_in[11];
    const float* b_g1   = (const float*)d_in[12];
    const float* W_g2   = (const float*)d_in[13];
    const float* b_g2   = (const float*)d_in[14];
    const float* gamma  = (const float*)d_in[15];
    const float* beta   = (const float*)d_in[16];
    float* out = (float*)d_out;

    cudaFuncSetAttribute(lstm_mma_kernel, cudaFuncAttributeMaxDynamicSharedMemorySize, LSMEM);
    cudaFuncSetAttribute(fuse_mma_kernel, cudaFuncAttributeMaxDynamicSharedMemorySize, FSMEM);

    reorder_kernel<<<G4 + DIM, 128>>>(W_hh, W_ih, b_ih, b_hh, W_rel);
    lstm_mma_kernel<<<NCTA, LTPB, LSMEM>>>(traj);
    alpha_kernel<<<1, 32>>>(espeed, gconf, W_g1, b_g1, W_g2, b_g2);
    fuse_mma_kernel<<<BN/FM, LTPB, FSMEM>>>(tokens, habs, W_abs, gamma, beta, out);
}

// round 10
// speedup vs baseline: 1.8517x; 1.0336x over previous
#include <cuda_runtime.h>
#include <cuda_bf16.h>
#include <cuda_fp16.h>
#include <math.h>
#include <stdint.h>
#include <string.h>

// ---------------- problem constants ----------------
#define BN      16384
#define HIDN    512
#define G4      2048
#define HLEN    15
#define DIM     1024

// ---------------- LSTM mma bf16 config ----------------
#define LTPB    256            // 8 warps
#define LM      64             // rows per CTA
#define NCTA    (BN/LM)        // 256 CTAs
#define KSLN    33             // K slices: 512 h + 16 (x,1,pad)
#define HRW     268            // h row stride in u32 words (=536 bf16); 268%32=12 -> conflict-free

// LSTM smem layout (bytes)
#define OFF_H0   0              // 64*536*2 = 68608
#define OFF_H1   68608
#define OFF_C    137216         // c fp16 [128 items][256 tid] = 65536
#define OFF_TRJ  202752         // 64*60*4 = 15360
#define LSMEM    218112

// fuse_mma smem layout (bytes)
#define FHW      260            // fuse h row stride (u32 words)
#define FO_HS    0              // 64*260*4 = 66560
#define FO_HB    66560
#define FO_RS    67072
#define FO_RQ    75264
#define FO_MU    83456
#define FO_RV    83712
#define FSMEM    83968
#define FM       64

// ---------------- device scratch ----------------
__device__ float    g_hn [BN * HIDN];              // final hidden (fp32)
__device__ float    g_alpha[32];
__device__ uint32_t g_Wf [4*KSLN*8*8*32*2];        // W_hh+W_ih+bias bf16x2 fragment order
__device__ uint32_t g_Wrf[DIM * HIDN / 2];         // W_rel bf16x2 fragment order

// ---------------- helpers ----------------
__device__ __forceinline__ float tanh_ap(float x){
    float y; asm("tanh.approx.f32 %0, %1;" : "=f"(y) : "f"(x)); return y;
}
__device__ __forceinline__ float sig_ap(float x){
    return fmaf(tanh_ap(0.5f*x), 0.5f, 0.5f);
}
#define MMA_BF16(c, a, b0, b1) \
    asm volatile("mma.sync.aligned.m16n8k16.row.col.f32.bf16.bf16.f32 " \
        "{%0,%1,%2,%3}, {%4,%5,%6,%7}, {%8,%9}, {%0,%1,%2,%3};" \
        : "+f"((c)[0]), "+f"((c)[1]), "+f"((c)[2]), "+f"((c)[3]) \
        : "r"((a)[0]), "r"((a)[1]), "r"((a)[2]), "r"((a)[3]), "r"(b0), "r"(b1))

__device__ __forceinline__ uint32_t bf2(float a, float b){
    __nv_bfloat162 p = __floats2bfloat162_rn(a, b);
    uint32_t u; memcpy(&u, &p, 4); return u;
}

// ---------------------------------------------------------------------------
// reorder: W_hh (+W_ih+bias slice 32) -> g_Wf; W_rel -> g_Wrf.
// blocks 0..2047 : gate cols (permuted); blocks 2048..3071 : W_rel cols.
// ---------------------------------------------------------------------------
__global__ void reorder_kernel(const float* __restrict__ Whh, const float* __restrict__ Wih,
                               const float* __restrict__ bih, const float* __restrict__ bhh,
                               const float* __restrict__ Wrel)
{
    if (blockIdx.x < G4) {
        int n = blockIdx.x;
        int cw = n & 63, chunk = n >> 6;
        int j = cw >> 3, qq = (cw >> 1) & 3, r = cw & 1;
        int gate, ul;
        if (j < 4) { ul = j*4 + qq;     gate = r;     }
        else       { ul = (j-4)*4 + qq; gate = 2 + r; }
        int srow = gate * HIDN + chunk * 16 + ul;

        const float* src = Whh + (size_t)srow * HIDN;
        int pass = n >> 9, w = (n >> 6) & 7, nt = (n >> 3) & 7, g8 = n & 7;
        float bsum = bih[srow] + bhh[srow];

        for (int k2 = threadIdx.x; k2 < (KSLN*16)/2; k2 += blockDim.x) {
            int k = k2 * 2;
            int ksl = k >> 4, kin = k & 15;
            float v0, v1;
            if (ksl < 32) { v0 = src[k]; v1 = src[k+1]; }
            else {
                v0 = (kin < 4) ? Wih[srow*4 + kin] : (kin == 4 ? bsum : 0.0f);
                v1 = (kin + 1 < 4) ? Wih[srow*4 + kin + 1] : 0.0f;
            }
            int jj = kin >> 3, qk = (kin >> 1) & 3;
            int lane = g8*4 + qk;
            size_t idx = ((((((size_t)pass*KSLN + ksl)*8 + w)*8 + nt)*32 + lane)*2 + jj);
            g_Wf[idx] = bf2(v0, v1);
        }
    } else {
        int n = blockIdx.x - G4;            // output col 0..1023
        const float* src = Wrel + (size_t)n * HIDN;
        int w = n >> 7, ch = (n >> 6) & 1, nt = (n >> 3) & 7, g8 = n & 7;
        for (int k2 = threadIdx.x; k2 < HIDN/2; k2 += blockDim.x) {
            int k = k2 * 2;
            int ksl = k >> 4, kin = k & 15;
            int jj = kin >> 3, qk = (kin >> 1) & 3;
            int lane = g8*4 + qk;
            size_t idx = ((((((size_t)(w*2 + ch))*32 + ksl)*8 + nt)*32 + lane)*2 + jj);
            g_Wrf[idx] = bf2(src[k], src[k+1]);
        }
    }
}

// ---------------------------------------------------------------------------
// LSTM via mma.sync bf16, K=528 (x & bias folded into GEMM), c fp16 in smem.
// 256 CTAs x 256 threads; 64 rows each; one barrier per timestep.
// ---------------------------------------------------------------------------
__global__ __launch_bounds__(LTPB, 1)
void lstm_mma_kernel(const float* __restrict__ traj)   // (BN,15,4)
{
    extern __shared__ char smem[];
    float*  trj = (float*) (smem + OFF_TRJ);   // [64][60]
    __half* c_s = (__half*)(smem + OFF_C);     // [128][256]

    const int tid = threadIdx.x;
    const int lane = tid & 31, warpid = tid >> 5;
    const int q = lane & 3, g8 = lane >> 2;
    const int m0 = blockIdx.x * LM;

    // one-time stage trajectories
    for (int i = tid; i < (LM*HLEN*4)/4; i += LTPB)
        ((float4*)trj)[i] = ((const float4*)(traj + (size_t)m0 * (HLEN*4)))[i];
    // x_0 + 1.0 + zeros into H0 cols 512..527 (direct from global, no dep on trj)
    if (tid < LM) {
        float4 xv = *(const float4*)(traj + (size_t)(m0 + tid) * (HLEN*4));
        uint32_t* dst = (uint32_t*)(smem + OFF_H0) + tid*HRW + 256;
        dst[0] = bf2(xv.x, xv.y); dst[1] = bf2(xv.z, xv.w); dst[2] = bf2(1.0f, 0.0f);
        dst[3] = 0; dst[4] = 0; dst[5] = 0; dst[6] = 0; dst[7] = 0;
    }
    __syncthreads();

    const uint2* __restrict__ Wf64 = (const uint2*)g_Wf;

    for (int t = 0; t < HLEN; ++t) {
        const uint32_t* hcur = (const uint32_t*)(smem + ((t & 1) ? OFF_H1 : OFF_H0));
        char*           hnb  = smem + ((t & 1) ? OFF_H0 : OFF_H1);
        __nv_bfloat16*  hnxt = (__nv_bfloat16*)hnb;

        for (int ncp = 0; ncp < 4; ++ncp) {
            float acc[4][8][4];
            #pragma unroll
            for (int mt = 0; mt < 4; ++mt)
                #pragma unroll
                for (int nt = 0; nt < 8; ++nt)
                    #pragma unroll
                    for (int c = 0; c < 4; ++c) acc[mt][nt][c] = 0.0f;

            const int ks0 = (t == 0) ? (KSLN - 1) : 0;
            const uint2* Bp = Wf64 + ((((size_t)ncp*KSLN)*8 + warpid)*8)*32 + lane;
            uint2 bc[8], bn[8];
            #pragma unroll
            for (int nt = 0; nt < 8; ++nt) bc[nt] = Bp[(size_t)ks0*2048 + nt*32];

            for (int ksl = ks0; ksl < KSLN; ++ksl) {
                if (ksl < KSLN - 1) {
                    const uint2* Bn = Bp + (size_t)(ksl + 1) * 2048;
                    #pragma unroll
                    for (int nt = 0; nt < 8; ++nt) bn[nt] = Bn[nt*32];
                }
                uint32_t a[4][4];
                const int kw = ksl * 8 + q;
                #pragma unroll
                for (int mt = 0; mt < 4; ++mt) {
                    int r0 = (mt*16 + g8) * HRW + kw;
                    a[mt][0] = hcur[r0];
                    a[mt][1] = hcur[r0 + 8*HRW];
                    a[mt][2] = hcur[r0 + 4];
                    a[mt][3] = hcur[r0 + 8*HRW + 4];
                }
                #pragma unroll
                for (int nt = 0; nt < 8; ++nt) {
                    #pragma unroll
                    for (int mt = 0; mt < 4; ++mt)
                        MMA_BF16(acc[mt][nt], a[mt], bc[nt].x, bc[nt].y);
                }
                #pragma unroll
                for (int nt = 0; nt < 8; ++nt) bc[nt] = bn[nt];
            }

            // ---- epilogue: pure activations; c in smem fp16 ----
            #pragma unroll
            for (int j = 0; j < 4; ++j) {
                const int kg = ncp*128 + warpid*16 + j*4 + q;
                #pragma unroll
                for (int mt = 0; mt < 4; ++mt) {
                    #pragma unroll
                    for (int half = 0; half < 2; ++half) {
                        const int row = mt*16 + g8 + half*8;
                        const float gi = acc[mt][j  ][half*2  ];
                        const float gf = acc[mt][j  ][half*2+1];
                        const float gg = acc[mt][j+4][half*2  ];
                        const float go = acc[mt][j+4][half*2+1];
                        const int cidx = (ncp*32 + j*8 + mt*2 + half)*LTPB + tid;
                        float cp = (t > 0) ? __half2float(c_s[cidx]) : 0.0f;
                        float cn = sig_ap(gf) * cp + sig_ap(gi) * tanh_ap(gg);
                        c_s[cidx] = __float2half(cn);
                        float hn = sig_ap(go) * tanh_ap(cn);
                        hnxt[row*536 + kg] = __float2bfloat16_rn(hn);
                        if (t == HLEN - 1) g_hn[(size_t)(m0 + row)*HIDN + kg] = hn;
                    }
                }
            }
        }

        // stage x_{t+1} + 1.0 into hnxt cols 512..527
        if (t < HLEN - 1 && tid < LM) {
            float4 xv = *(const float4*)(trj + tid*60 + (t+1)*4);
            uint32_t* dst = (uint32_t*)hnb + tid*HRW + 256;
            dst[0] = bf2(xv.x, xv.y); dst[1] = bf2(xv.z, xv.w); dst[2] = bf2(1.0f, 0.0f);
            dst[3] = 0; dst[4] = 0; dst[5] = 0; dst[6] = 0; dst[7] = 0;
        }
        __syncthreads();
    }
}

// ---------------------------------------------------------------------------
__global__ void alpha_kernel(const float* __restrict__ ego_speed, const float* __restrict__ gps_conf,
                             const float* __restrict__ W_g1, const float* __restrict__ b_g1,
                             const float* __restrict__ W_g2, const float* __restrict__ b_g2)
{
    int b = threadIdx.x;
    if (b < 32) {
        float s = ego_speed[b], c = gps_conf[b];
        float acc = b_g2[0];
        #pragma unroll
        for (int h = 0; h < 16; ++h) {
            float t = W_g1[2*h]*s + W_g1[2*h+1]*c + b_g1[h];
            acc += W_g2[h] * fmaxf(t, 0.0f);
        }
        g_alpha[b] = 1.0f / (1.0f + expf(-acc));
    }
}

// ---------------------------------------------------------------------------
// fuse via mma.sync bf16 (unchanged, proven at ~132 us)
// ---------------------------------------------------------------------------
__global__ __launch_bounds__(LTPB, 1)
void fuse_mma_kernel(const float* __restrict__ tokens, const float* __restrict__ habs,
                     const float* __restrict__ W_abs,
                     const float* __restrict__ gamma, const float* __restrict__ beta,
                     float* __restrict__ out)
{
    extern __shared__ char smem[];
    uint32_t* hs   = (uint32_t*)(smem + FO_HS);
    float*    hb   = (float*)   (smem + FO_HB);
    float*    redS = (float*)   (smem + FO_RS);
    float*    redQ = (float*)   (smem + FO_RQ);
    float*    mu_s = (float*)   (smem + FO_MU);
    float*    rs_s = (float*)   (smem + FO_RV);

    const int tid = threadIdx.x;
    const int lane = tid & 31, warpid = tid >> 5;
    const int q = lane & 3, g8 = lane >> 2;
    const int m0 = blockIdx.x * FM;

    for (int i = tid; i < FM*256; i += LTPB) {
        int row = i >> 8, kw = i & 255;
        float2 v = ((const float2*)(g_hn + (size_t)(m0 + row)*HIDN))[kw];
        hs[row*FHW + kw] = bf2(v.x, v.y);
    }
    for (int i = tid; i < FM*2; i += LTPB) hb[i] = habs[(size_t)m0*2 + i];
    __syncthreads();

    const float al = g_alpha[m0 >> 9], ali = 1.0f - al;
    const uint2* __restrict__ Wr64 = (const uint2*)g_Wrf;

    float rsum[8], rq[8];
    #pragma unroll
    for (int s = 0; s < 8; ++s) { rsum[s] = 0.0f; rq[s] = 0.0f; }

    #pragma unroll
    for (int ch = 0; ch < 2; ++ch) {
        float acc[4][8][4];
        #pragma unroll
        for (int mt = 0; mt < 4; ++mt)
            #pragma unroll
            for (int nt = 0; nt < 8; ++nt)
                #pragma unroll
                for (int c = 0; c < 4; ++c) acc[mt][nt][c] = 0.0f;

        const uint2* Bp = Wr64 + ((size_t)(warpid*2 + ch)*32*8)*32 + lane;
        uint2 bc[8], bn[8];
        #pragma unroll
        for (int nt = 0; nt < 8; ++nt) bc[nt] = Bp[nt*32];

        for (int ksl = 0; ksl < 32; ++ksl) {
            if (ksl < 31) {
                const uint2* Bn = Bp + (size_t)(ksl + 1) * 256;
                #pragma unroll
                for (int nt = 0; nt < 8; ++nt) bn[nt] = Bn[nt*32];
            }
            uint32_t a[4][4];
            const int kw = ksl * 8 + q;
            #pragma unroll
            for (int mt = 0; mt < 4; ++mt) {
                int r0 = (mt*16 + g8) * FHW + kw;
                a[mt][0] = hs[r0];
                a[mt][1] = hs[r0 + 8*FHW];
                a[mt][2] = hs[r0 + 4];
                a[mt][3] = hs[r0 + 8*FHW + 4];
            }
            #pragma unroll
            for (int nt = 0; nt < 8; ++nt) {
                #pragma unroll
                for (int mt = 0; mt < 4; ++mt)
                    MMA_BF16(acc[mt][nt], a[mt], bc[nt].x, bc[nt].y);
            }
            #pragma unroll
            for (int nt = 0; nt < 8; ++nt) bc[nt] = bn[nt];
        }

        #pragma unroll
        for (int mt = 0; mt < 4; ++mt) {
            #pragma unroll
            for (int half = 0; half < 2; ++half) {
                const int row = mt*16 + g8 + half*8;
                const int R   = m0 + row;
                const float h0 = hb[row*2], h1 = hb[row*2+1];
                const int slot = mt*2 + half;
                #pragma unroll
                for (int nt = 0; nt < 8; ++nt) {
                    const int col = warpid*128 + ch*64 + nt*8 + q*2;
                    float2 tk  = *(const float2*)(tokens + (size_t)R*DIM + col);
                    float2 wa0 = ((const float2*)W_abs)[col];
                    float2 wa1 = ((const float2*)W_abs)[col+1];
                    float x0 = tk.x + al*acc[mt][nt][half*2  ] + ali*(h0*wa0.x + h1*wa0.y);
                    float x1 = tk.y + al*acc[mt][nt][half*2+1] + ali*(h0*wa1.x + h1*wa1.y);
                    *(float2*)(out + (size_t)R*DIM + col) = make_float2(x0, x1);
                    rsum[slot] += x0 + x1;
                    rq[slot]   += x0*x0 + x1*x1;
                }
            }
        }
    }

    __syncthreads();
    #pragma unroll
    for (int mt = 0; mt < 4; ++mt)
        #pragma unroll
        for (int half = 0; half < 2; ++half) {
            const int row = mt*16 + g8 + half*8;
            redS[row*32 + warpid*4 + q] = rsum[mt*2 + half];
            redQ[row*32 + warpid*4 + q] = rq[mt*2 + half];
        }
    __syncthreads();
    if (tid < FM) {
        float s = 0.0f, qq = 0.0f;
        #pragma unroll
        for (int i = 0; i < 32; ++i) { s += redS[tid*32 + i]; qq += redQ[tid*32 + i]; }
        float mu = s * (1.0f/DIM);
        float var = qq * (1.0f/DIM) - mu*mu;
        mu_s[tid] = mu; rs_s[tid] = rsqrtf(var + 1e-5f);
    }
    __syncthreads();

    for (int i = tid; i < (FM*DIM)/4; i += LTPB) {
        int mm = i >> 8, j4 = i & 255;
        float4 v = ((float4*)(out + (size_t)(m0 + mm)*DIM))[j4];
        float4 g = ((const float4*)gamma)[j4];
        float4 b = ((const float4*)beta)[j4];
        float mu = mu_s[mm], rr = rs_s[mm];
        v.x = (v.x - mu)*rr*g.x + b.x;
        v.y = (v.y - mu)*rr*g.y + b.y;
        v.z = (v.z - mu)*rr*g.z + b.z;
        v.w = (v.w - mu)*rr*g.w + b.w;
        ((float4*)(out + (size_t)(m0 + mm)*DIM))[j4] = v;
    }
}

// ---------------------------------------------------------------------------
extern "C" void kernel_launch(void* const* d_in, const int* in_sizes, int n_in,
                              void* d_out, int out_size)
{
    const float* tokens = (const float*)d_in[0];
    const float* traj   = (const float*)d_in[1];
    const float* habs   = (const float*)d_in[2];
    const float* espeed = (const float*)d_in[3];
    const float* gconf  = (const float*)d_in[4];
    const float* W_ih   = (const float*)d_in[5];
    const float* W_hh   = (const float*)d_in[6];
    const float* b_ih   = (const float*)d_in[7];
    const float* b_hh   = (const float*)d_in[8];
    const float* W_rel  = (const float*)d_in[9];
    const float* W_abs  = (const float*)d_in[10];
    const float* W_g1   = (const float*)d_in[11];
    const float* b_g1   = (const float*)d_in[12];
    const float* W_g2   = (const float*)d_in[13];
    const float* b_g2   = (const float*)d_in[14];
    const float* gamma  = (const float*)d_in[15];
    const float* beta   = (const float*)d_in[16];
    float* out = (float*)d_out;

    cudaFuncSetAttribute(lstm_mma_kernel, cudaFuncAttributeMaxDynamicSharedMemorySize, LSMEM);
    cudaFuncSetAttribute(fuse_mma_kernel, cudaFuncAttributeMaxDynamicSharedMemorySize, FSMEM);

    reorder_kernel<<<G4 + DIM, 128>>>(W_hh, W_ih, b_ih, b_hh, W_rel);
    lstm_mma_kernel<<<NCTA, LTPB, LSMEM>>>(traj);
    alpha_kernel<<<1, 32>>>(espeed, gconf, W_g1, b_g1, W_g2, b_g2);
    fuse_mma_kernel<<<BN/FM, LTPB, FSMEM>>>(tokens, habs, W_abs, gamma, beta, out);
}

// round 11
// speedup vs baseline: 2.3779x; 1.2842x over previous
#include <cuda_runtime.h>
#include <cuda_bf16.h>
#include <cuda_fp16.h>
#include <math.h>
#include <stdint.h>
#include <string.h>

// ---------------- problem constants ----------------
#define BN      16384
#define HIDN    512
#define G4      2048
#define HLEN    15
#define DIM     1024

// ---------------- LSTM mma bf16 config ----------------
#define LTPB    512            // 16 warps (4 per SMSP)
#define LM      64             // rows per CTA
#define NCTA    (BN/LM)        // 256 CTAs
#define KSLN    33             // K slices: 512 h + 16 (x,1,pad)
#define HRW     268            // h row stride in u32 words (=536 bf16); conflict-free

// LSTM smem layout (bytes)
#define OFF_H0   0              // 64*536*2 = 68608
#define OFF_H1   68608
#define OFF_C    137216         // c fp16 [64 slots][512 tid] = 65536
#define OFF_TRJ  202752         // 64*60*4 = 15360
#define LSMEM    218112

// fuse_mma smem layout (bytes) — unchanged
#define FTPB     256
#define FHW      260
#define FO_HS    0
#define FO_HB    66560
#define FO_RS    67072
#define FO_RQ    75264
#define FO_MU    83456
#define FO_RV    83712
#define FSMEM    83968
#define FM       64

// ---------------- device scratch ----------------
__device__ float    g_hn [BN * HIDN];              // final hidden (fp32)
__device__ float    g_alpha[32];
__device__ uint32_t g_Wf [4*KSLN*16*4*32*2];       // W_hh+W_ih+bias bf16x2 fragment order (16-warp layout)
__device__ uint32_t g_Wrf[DIM * HIDN / 2];         // W_rel bf16x2 fragment order (fuse layout)

// ---------------- helpers ----------------
__device__ __forceinline__ float tanh_ap(float x){
    float y; asm("tanh.approx.f32 %0, %1;" : "=f"(y) : "f"(x)); return y;
}
__device__ __forceinline__ float sig_ap(float x){
    return fmaf(tanh_ap(0.5f*x), 0.5f, 0.5f);
}
#define MMA_BF16(c, a, b0, b1) \
    asm volatile("mma.sync.aligned.m16n8k16.row.col.f32.bf16.bf16.f32 " \
        "{%0,%1,%2,%3}, {%4,%5,%6,%7}, {%8,%9}, {%0,%1,%2,%3};" \
        : "+f"((c)[0]), "+f"((c)[1]), "+f"((c)[2]), "+f"((c)[3]) \
        : "r"((a)[0]), "r"((a)[1]), "r"((a)[2]), "r"((a)[3]), "r"(b0), "r"(b1))

__device__ __forceinline__ uint32_t bf2(float a, float b){
    __nv_bfloat162 p = __floats2bfloat162_rn(a, b);
    uint32_t u; memcpy(&u, &p, 4); return u;
}

// ---------------------------------------------------------------------------
// reorder.
// W_hh branch (blocks 0..2047): 16-warp / 32-col-chunk gate permutation.
//   n: pass=n>>9, w16=(n>>5)&15, cw=n&31; j=cw>>3 (n-tile 0..3), qq=(cw>>1)&3, r=cw&1.
//   j<2: unit_local=j*4+qq, gate=r;  j>=2: unit_local=(j-2)*4+qq, gate=2+r.
//   unit = pass*128 + w16*8 + unit_local; srow = gate*512 + unit.
//   Slice 32 carries [W_ih(4), bias, 0...] so xg+bias ride the GEMM.
//   Storage (u32): ((((pass*KSLN+ksl)*16+w16)*4+j)*32 + (cw&7)*4+qk)*2 + jj
// W_rel branch (blocks 2048..3071): unchanged fuse layout.
// ---------------------------------------------------------------------------
__global__ void reorder_kernel(const float* __restrict__ Whh, const float* __restrict__ Wih,
                               const float* __restrict__ bih, const float* __restrict__ bhh,
                               const float* __restrict__ Wrel)
{
    if (blockIdx.x < G4) {
        int n = blockIdx.x;
        int pass = n >> 9, w16 = (n >> 5) & 15, cw = n & 31;
        int j = cw >> 3, qq = (cw >> 1) & 3, r = cw & 1;
        int gate, ul;
        if (j < 2) { ul = j*4 + qq;     gate = r;     }
        else       { ul = (j-2)*4 + qq; gate = 2 + r; }
        int unit = pass*128 + w16*8 + ul;
        int srow = gate * HIDN + unit;

        const float* src = Whh + (size_t)srow * HIDN;
        float bsum = bih[srow] + bhh[srow];
        int colin = cw & 7;                    // col within 8-wide n-tile

        for (int k2 = threadIdx.x; k2 < (KSLN*16)/2; k2 += blockDim.x) {
            int k = k2 * 2;
            int ksl = k >> 4, kin = k & 15;
            float v0, v1;
            if (ksl < 32) { v0 = src[k]; v1 = src[k+1]; }
            else {
                v0 = (kin < 4) ? Wih[srow*4 + kin] : (kin == 4 ? bsum : 0.0f);
                v1 = (kin + 1 < 4) ? Wih[srow*4 + kin + 1] : 0.0f;
            }
            int jj = kin >> 3, qk = (kin >> 1) & 3;
            int lane = colin*4 + qk;
            size_t idx = ((((((size_t)pass*KSLN + ksl)*16 + w16)*4 + j)*32 + lane)*2 + jj);
            g_Wf[idx] = bf2(v0, v1);
        }
    } else {
        int n = blockIdx.x - G4;            // output col 0..1023
        const float* src = Wrel + (size_t)n * HIDN;
        int w = n >> 7, ch = (n >> 6) & 1, nt = (n >> 3) & 7, g8 = n & 7;
        for (int k2 = threadIdx.x; k2 < HIDN/2; k2 += blockDim.x) {
            int k = k2 * 2;
            int ksl = k >> 4, kin = k & 15;
            int jj = kin >> 3, qk = (kin >> 1) & 3;
            int lane = g8*4 + qk;
            size_t idx = ((((((size_t)(w*2 + ch))*32 + ksl)*8 + nt)*32 + lane)*2 + jj);
            g_Wrf[idx] = bf2(src[k], src[k+1]);
        }
    }
}

// ---------------------------------------------------------------------------
// LSTM via mma.sync bf16, K=528, c fp16 in smem, 16 warps (warp tile 64x32).
// 256 CTAs x 512 threads; 64 rows each; one barrier per timestep.
// ---------------------------------------------------------------------------
__global__ __launch_bounds__(LTPB, 1)
void lstm_mma_kernel(const float* __restrict__ traj)   // (BN,15,4)
{
    extern __shared__ char smem[];
    float*  trj = (float*) (smem + OFF_TRJ);   // [64][60]
    __half* c_s = (__half*)(smem + OFF_C);     // [64][512]

    const int tid = threadIdx.x;
    const int lane = tid & 31, warpid = tid >> 5;   // 0..15
    const int q = lane & 3, g8 = lane >> 2;
    const int m0 = blockIdx.x * LM;

    // one-time stage trajectories
    for (int i = tid; i < (LM*HLEN*4)/4; i += LTPB)
        ((float4*)trj)[i] = ((const float4*)(traj + (size_t)m0 * (HLEN*4)))[i];
    // x_0 + 1.0 + zeros into H0 cols 512..527
    if (tid < LM) {
        float4 xv = *(const float4*)(traj + (size_t)(m0 + tid) * (HLEN*4));
        uint32_t* dst = (uint32_t*)(smem + OFF_H0) + tid*HRW + 256;
        dst[0] = bf2(xv.x, xv.y); dst[1] = bf2(xv.z, xv.w); dst[2] = bf2(1.0f, 0.0f);
        dst[3] = 0; dst[4] = 0; dst[5] = 0; dst[6] = 0; dst[7] = 0;
    }
    __syncthreads();

    const uint2* __restrict__ Wf64 = (const uint2*)g_Wf;

    for (int t = 0; t < HLEN; ++t) {
        const uint32_t* hcur = (const uint32_t*)(smem + ((t & 1) ? OFF_H1 : OFF_H0));
        char*           hnb  = smem + ((t & 1) ? OFF_H0 : OFF_H1);
        __nv_bfloat16*  hnxt = (__nv_bfloat16*)hnb;

        for (int ncp = 0; ncp < 4; ++ncp) {
            float acc[4][4][4];
            #pragma unroll
            for (int mt = 0; mt < 4; ++mt)
                #pragma unroll
                for (int nt = 0; nt < 4; ++nt)
                    #pragma unroll
                    for (int c = 0; c < 4; ++c) acc[mt][nt][c] = 0.0f;

            const int ks0 = (t == 0) ? (KSLN - 1) : 0;
            // u64 index: (((pass*KSLN+ksl)*16 + w16)*4 + nt)*32 + lane
            const uint2* Bp = Wf64 + (((size_t)ncp*KSLN*16 + warpid)*4)*32 + lane;
            uint2 bc[4], bn[4];
            #pragma unroll
            for (int nt = 0; nt < 4; ++nt) bc[nt] = Bp[(size_t)ks0*2048 + nt*32];

            for (int ksl = ks0; ksl < KSLN; ++ksl) {
                if (ksl < KSLN - 1) {
                    const uint2* Bn = Bp + (size_t)(ksl + 1) * 2048;
                    #pragma unroll
                    for (int nt = 0; nt < 4; ++nt) bn[nt] = Bn[nt*32];
                }
                uint32_t a[4][4];
                const int kw = ksl * 8 + q;
                #pragma unroll
                for (int mt = 0; mt < 4; ++mt) {
                    int r0 = (mt*16 + g8) * HRW + kw;
                    a[mt][0] = hcur[r0];
                    a[mt][1] = hcur[r0 + 8*HRW];
                    a[mt][2] = hcur[r0 + 4];
                    a[mt][3] = hcur[r0 + 8*HRW + 4];
                }
                #pragma unroll
                for (int nt = 0; nt < 4; ++nt) {
                    #pragma unroll
                    for (int mt = 0; mt < 4; ++mt)
                        MMA_BF16(acc[mt][nt], a[mt], bc[nt].x, bc[nt].y);
                }
                #pragma unroll
                for (int nt = 0; nt < 4; ++nt) bc[nt] = bn[nt];
            }

            // ---- epilogue: 2 units/thread per (mt,half); c in smem fp16 ----
            #pragma unroll
            for (int j2 = 0; j2 < 2; ++j2) {
                const int kg = ncp*128 + warpid*8 + j2*4 + q;
                #pragma unroll
                for (int mt = 0; mt < 4; ++mt) {
                    #pragma unroll
                    for (int half = 0; half < 2; ++half) {
                        const int row = mt*16 + g8 + half*8;
                        const float gi = acc[mt][j2  ][half*2  ];
                        const float gf = acc[mt][j2  ][half*2+1];
                        const float gg = acc[mt][j2+2][half*2  ];
                        const float go = acc[mt][j2+2][half*2+1];
                        const int cidx = ((ncp*2 + j2)*8 + mt*2 + half)*LTPB + tid;
                        float cp = (t > 0) ? __half2float(c_s[cidx]) : 0.0f;
                        float cn = sig_ap(gf) * cp + sig_ap(gi) * tanh_ap(gg);
                        c_s[cidx] = __float2half(cn);
                        float hn = sig_ap(go) * tanh_ap(cn);
                        hnxt[row*536 + kg] = __float2bfloat16_rn(hn);
                        if (t == HLEN - 1) g_hn[(size_t)(m0 + row)*HIDN + kg] = hn;
                    }
                }
            }
        }

        // stage x_{t+1} + 1.0 into hnxt cols 512..527
        if (t < HLEN - 1 && tid < LM) {
            float4 xv = *(const float4*)(trj + tid*60 + (t+1)*4);
            uint32_t* dst = (uint32_t*)hnb + tid*HRW + 256;
            dst[0] = bf2(xv.x, xv.y); dst[1] = bf2(xv.z, xv.w); dst[2] = bf2(1.0f, 0.0f);
            dst[3] = 0; dst[4] = 0; dst[5] = 0; dst[6] = 0; dst[7] = 0;
        }
        __syncthreads();
    }
}

// ---------------------------------------------------------------------------
__global__ void alpha_kernel(const float* __restrict__ ego_speed, const float* __restrict__ gps_conf,
                             const float* __restrict__ W_g1, const float* __restrict__ b_g1,
                             const float* __restrict__ W_g2, const float* __restrict__ b_g2)
{
    int b = threadIdx.x;
    if (b < 32) {
        float s = ego_speed[b], c = gps_conf[b];
        float acc = b_g2[0];
        #pragma unroll
        for (int h = 0; h < 16; ++h) {
            float t = W_g1[2*h]*s + W_g1[2*h+1]*c + b_g1[h];
            acc += W_g2[h] * fmaxf(t, 0.0f);
        }
        g_alpha[b] = 1.0f / (1.0f + expf(-acc));
    }
}

// ---------------------------------------------------------------------------
// fuse via mma.sync bf16 (unchanged, proven at ~132 us)
// ---------------------------------------------------------------------------
__global__ __launch_bounds__(FTPB, 1)
void fuse_mma_kernel(const float* __restrict__ tokens, const float* __restrict__ habs,
                     const float* __restrict__ W_abs,
                     const float* __restrict__ gamma, const float* __restrict__ beta,
                     float* __restrict__ out)
{
    extern __shared__ char smem[];
    uint32_t* hs   = (uint32_t*)(smem + FO_HS);
    float*    hb   = (float*)   (smem + FO_HB);
    float*    redS = (float*)   (smem + FO_RS);
    float*    redQ = (float*)   (smem + FO_RQ);
    float*    mu_s = (float*)   (smem + FO_MU);
    float*    rs_s = (float*)   (smem + FO_RV);

    const int tid = threadIdx.x;
    const int lane = tid & 31, warpid = tid >> 5;
    const int q = lane & 3, g8 = lane >> 2;
    const int m0 = blockIdx.x * FM;

    for (int i = tid; i < FM*256; i += FTPB) {
        int row = i >> 8, kw = i & 255;
        float2 v = ((const float2*)(g_hn + (size_t)(m0 + row)*HIDN))[kw];
        hs[row*FHW + kw] = bf2(v.x, v.y);
    }
    for (int i = tid; i < FM*2; i += FTPB) hb[i] = habs[(size_t)m0*2 + i];
    __syncthreads();

    const float al = g_alpha[m0 >> 9], ali = 1.0f - al;
    const uint2* __restrict__ Wr64 = (const uint2*)g_Wrf;

    float rsum[8], rq[8];
    #pragma unroll
    for (int s = 0; s < 8; ++s) { rsum[s] = 0.0f; rq[s] = 0.0f; }

    #pragma unroll
    for (int ch = 0; ch < 2; ++ch) {
        float acc[4][8][4];
        #pragma unroll
        for (int mt = 0; mt < 4; ++mt)
            #pragma unroll
            for (int nt = 0; nt < 8; ++nt)
                #pragma unroll
                for (int c = 0; c < 4; ++c) acc[mt][nt][c] = 0.0f;

        const uint2* Bp = Wr64 + ((size_t)(warpid*2 + ch)*32*8)*32 + lane;
        uint2 bc[8], bn[8];
        #pragma unroll
        for (int nt = 0; nt < 8; ++nt) bc[nt] = Bp[nt*32];

        for (int ksl = 0; ksl < 32; ++ksl) {
            if (ksl < 31) {
                const uint2* Bn = Bp + (size_t)(ksl + 1) * 256;
                #pragma unroll
                for (int nt = 0; nt < 8; ++nt) bn[nt] = Bn[nt*32];
            }
            uint32_t a[4][4];
            const int kw = ksl * 8 + q;
            #pragma unroll
            for (int mt = 0; mt < 4; ++mt) {
                int r0 = (mt*16 + g8) * FHW + kw;
                a[mt][0] = hs[r0];
                a[mt][1] = hs[r0 + 8*FHW];
                a[mt][2] = hs[r0 + 4];
                a[mt][3] = hs[r0 + 8*FHW + 4];
            }
            #pragma unroll
            for (int nt = 0; nt < 8; ++nt) {
                #pragma unroll
                for (int mt = 0; mt < 4; ++mt)
                    MMA_BF16(acc[mt][nt], a[mt], bc[nt].x, bc[nt].y);
            }
            #pragma unroll
            for (int nt = 0; nt < 8; ++nt) bc[nt] = bn[nt];
        }

        #pragma unroll
        for (int mt = 0; mt < 4; ++mt) {
            #pragma unroll
            for (int half = 0; half < 2; ++half) {
                const int row = mt*16 + g8 + half*8;
                const int R   = m0 + row;
                const float h0 = hb[row*2], h1 = hb[row*2+1];
                const int slot = mt*2 + half;
                #pragma unroll
                for (int nt = 0; nt < 8; ++nt) {
                    const int col = warpid*128 + ch*64 + nt*8 + q*2;
                    float2 tk  = *(const float2*)(tokens + (size_t)R*DIM + col);
                    float2 wa0 = ((const float2*)W_abs)[col];
                    float2 wa1 = ((const float2*)W_abs)[col+1];
                    float x0 = tk.x + al*acc[mt][nt][half*2  ] + ali*(h0*wa0.x + h1*wa0.y);
                    float x1 = tk.y + al*acc[mt][nt][half*2+1] + ali*(h0*wa1.x + h1*wa1.y);
                    *(float2*)(out + (size_t)R*DIM + col) = make_float2(x0, x1);
                    rsum[slot] += x0 + x1;
                    rq[slot]   += x0*x0 + x1*x1;
                }
            }
        }
    }

    __syncthreads();
    #pragma unroll
    for (int mt = 0; mt < 4; ++mt)
        #pragma unroll
        for (int half = 0; half < 2; ++half) {
            const int row = mt*16 + g8 + half*8;
            redS[row*32 + warpid*4 + q] = rsum[mt*2 + half];
            redQ[row*32 + warpid*4 + q] = rq[mt*2 + half];
        }
    __syncthreads();
    if (tid < FM) {
        float s = 0.0f, qq = 0.0f;
        #pragma unroll
        for (int i = 0; i < 32; ++i) { s += redS[tid*32 + i]; qq += redQ[tid*32 + i]; }
        float mu = s * (1.0f/DIM);
        float var = qq * (1.0f/DIM) - mu*mu;
        mu_s[tid] = mu; rs_s[tid] = rsqrtf(var + 1e-5f);
    }
    __syncthreads();

    for (int i = tid; i < (FM*DIM)/4; i += FTPB) {
        int mm = i >> 8, j4 = i & 255;
        float4 v = ((float4*)(out + (size_t)(m0 + mm)*DIM))[j4];
        float4 g = ((const float4*)gamma)[j4];
        float4 b = ((const float4*)beta)[j4];
        float mu = mu_s[mm], rr = rs_s[mm];
        v.x = (v.x - mu)*rr*g.x + b.x;
        v.y = (v.y - mu)*rr*g.y + b.y;
        v.z = (v.z - mu)*rr*g.z + b.z;
        v.w = (v.w - mu)*rr*g.w + b.w;
        ((float4*)(out + (size_t)(m0 + mm)*DIM))[j4] = v;
    }
}

// ---------------------------------------------------------------------------
extern "C" void kernel_launch(void* const* d_in, const int* in_sizes, int n_in,
                              void* d_out, int out_size)
{
    const float* tokens = (const float*)d_in[0];
    const float* traj   = (const float*)d_in[1];
    const float* habs   = (const float*)d_in[2];
    const float* espeed = (const float*)d_in[3];
    const float* gconf  = (const float*)d_in[4];
    const float* W_ih   = (const float*)d_in[5];
    const float* W_hh   = (const float*)d_in[6];
    const float* b_ih   = (const float*)d_in[7];
    const float* b_hh   = (const float*)d_in[8];
    const float* W_rel  = (const float*)d_in[9];
    const float* W_abs  = (const float*)d_in[10];
    const float* W_g1   = (const float*)d_in[11];
    const float* b_g1   = (const float*)d_in[12];
    const float* W_g2   = (const float*)d_in[13];
    const float* b_g2   = (const float*)d_in[14];
    const float* gamma  = (const float*)d_in[15];
    const float* beta   = (const float*)d_in[16];
    float* out = (float*)d_out;

    cudaFuncSetAttribute(lstm_mma_kernel, cudaFuncAttributeMaxDynamicSharedMemorySize, LSMEM);
    cudaFuncSetAttribute(fuse_mma_kernel, cudaFuncAttributeMaxDynamicSharedMemorySize, FSMEM);

    reorder_kernel<<<G4 + DIM, 128>>>(W_hh, W_ih, b_ih, b_hh, W_rel);
    lstm_mma_kernel<<<NCTA, LTPB, LSMEM>>>(traj);
    alpha_kernel<<<1, 32>>>(espeed, gconf, W_g1, b_g1, W_g2, b_g2);
    fuse_mma_kernel<<<BN/FM, FTPB, FSMEM>>>(tokens, habs, W_abs, gamma, beta, out);
}

// round 12
// speedup vs baseline: 2.4896x; 1.0470x over previous
#include <cuda_runtime.h>
#include <cuda_bf16.h>
#include <cuda_fp16.h>
#include <math.h>
#include <stdint.h>
#include <string.h>

// ---------------- problem constants ----------------
#define BN      16384
#define HIDN    512
#define G4      2048
#define HLEN    15
#define DIM     1024

// ---------------- LSTM mma bf16 config ----------------
#define LTPB    512            // 16 warps (4 per SMSP)
#define LM      64             // rows per CTA
#define NCTA    (BN/LM)        // 256 CTAs
#define KSLN    33             // K slices: 512 h + 16 (x,1,pad)
#define HRW     268            // h row stride in u32 words (=536 bf16); conflict-free

// LSTM smem layout (bytes)
#define OFF_H0   0              // 64*536*2 = 68608
#define OFF_H1   68608
#define OFF_C    137216         // c fp16 [64 slots][512 tid] = 65536
#define OFF_TRJ  202752         // 64*60*4 = 15360
#define LSMEM    218112

// fuse_mma smem layout (bytes) — unchanged
#define FTPB     256
#define FHW      260
#define FO_HS    0
#define FO_HB    66560
#define FO_RS    67072
#define FO_RQ    75264
#define FO_MU    83456
#define FO_RV    83712
#define FSMEM    83968
#define FM       64

// ---------------- device scratch ----------------
__device__ float    g_hn [BN * HIDN];              // final hidden (fp32)
__device__ float    g_alpha[32];
__device__ uint32_t g_Wf [4*KSLN*16*4*32*2];       // W_hh+W_ih+bias bf16x2 fragment order
__device__ uint32_t g_Wrf[DIM * HIDN / 2];         // W_rel bf16x2 fragment order

// ---------------- helpers ----------------
__device__ __forceinline__ float tanh_ap(float x){
    float y; asm("tanh.approx.f32 %0, %1;" : "=f"(y) : "f"(x)); return y;
}
__device__ __forceinline__ float sig_ap(float x){
    return fmaf(tanh_ap(0.5f*x), 0.5f, 0.5f);
}
__device__ __forceinline__ uint32_t smem_u32(const void* p){
    uint32_t a; asm("{ .reg .u64 t; cvta.to.shared.u64 t, %1; cvt.u32.u64 %0, t; }":"=r"(a):"l"(p)); return a;
}
#define MMA_BF16(c, a, b0, b1) \
    asm volatile("mma.sync.aligned.m16n8k16.row.col.f32.bf16.bf16.f32 " \
        "{%0,%1,%2,%3}, {%4,%5,%6,%7}, {%8,%9}, {%0,%1,%2,%3};" \
        : "+f"((c)[0]), "+f"((c)[1]), "+f"((c)[2]), "+f"((c)[3]) \
        : "r"((a)[0]), "r"((a)[1]), "r"((a)[2]), "r"((a)[3]), "r"(b0), "r"(b1))
#define LDSM4(r, addr) \
    asm volatile("ldmatrix.sync.aligned.m8n8.x4.shared.b16 {%0,%1,%2,%3}, [%4];" \
        : "=r"((r)[0]), "=r"((r)[1]), "=r"((r)[2]), "=r"((r)[3]) : "r"(addr))

__device__ __forceinline__ uint32_t bf2(float a, float b){
    __nv_bfloat162 p = __floats2bfloat162_rn(a, b);
    uint32_t u; memcpy(&u, &p, 4); return u;
}

// ---------------------------------------------------------------------------
// reorder (unchanged from R11 — proven).
// ---------------------------------------------------------------------------
__global__ void reorder_kernel(const float* __restrict__ Whh, const float* __restrict__ Wih,
                               const float* __restrict__ bih, const float* __restrict__ bhh,
                               const float* __restrict__ Wrel)
{
    if (blockIdx.x < G4) {
        int n = blockIdx.x;
        int pass = n >> 9, w16 = (n >> 5) & 15, cw = n & 31;
        int j = cw >> 3, qq = (cw >> 1) & 3, r = cw & 1;
        int gate, ul;
        if (j < 2) { ul = j*4 + qq;     gate = r;     }
        else       { ul = (j-2)*4 + qq; gate = 2 + r; }
        int unit = pass*128 + w16*8 + ul;
        int srow = gate * HIDN + unit;

        const float* src = Whh + (size_t)srow * HIDN;
        float bsum = bih[srow] + bhh[srow];
        int colin = cw & 7;

        for (int k2 = threadIdx.x; k2 < (KSLN*16)/2; k2 += blockDim.x) {
            int k = k2 * 2;
            int ksl = k >> 4, kin = k & 15;
            float v0, v1;
            if (ksl < 32) { v0 = src[k]; v1 = src[k+1]; }
            else {
                v0 = (kin < 4) ? Wih[srow*4 + kin] : (kin == 4 ? bsum : 0.0f);
                v1 = (kin + 1 < 4) ? Wih[srow*4 + kin + 1] : 0.0f;
            }
            int jj = kin >> 3, qk = (kin >> 1) & 3;
            int lane = colin*4 + qk;
            size_t idx = ((((((size_t)pass*KSLN + ksl)*16 + w16)*4 + j)*32 + lane)*2 + jj);
            g_Wf[idx] = bf2(v0, v1);
        }
    } else {
        int n = blockIdx.x - G4;
        const float* src = Wrel + (size_t)n * HIDN;
        int w = n >> 7, ch = (n >> 6) & 1, nt = (n >> 3) & 7, g8 = n & 7;
        for (int k2 = threadIdx.x; k2 < HIDN/2; k2 += blockDim.x) {
            int k = k2 * 2;
            int ksl = k >> 4, kin = k & 15;
            int jj = kin >> 3, qk = (kin >> 1) & 3;
            int lane = g8*4 + qk;
            size_t idx = ((((((size_t)(w*2 + ch))*32 + ksl)*8 + nt)*32 + lane)*2 + jj);
            g_Wrf[idx] = bf2(src[k], src[k+1]);
        }
    }
}

// ---------------------------------------------------------------------------
// LSTM via mma.sync bf16, K=528, c fp16 in smem, 16 warps, ldmatrix A loads.
// ---------------------------------------------------------------------------
__global__ __launch_bounds__(LTPB, 1)
void lstm_mma_kernel(const float* __restrict__ traj)   // (BN,15,4)
{
    extern __shared__ char smem[];
    float*  trj = (float*) (smem + OFF_TRJ);   // [64][60]
    __half* c_s = (__half*)(smem + OFF_C);     // [64][512]

    const int tid = threadIdx.x;
    const int lane = tid & 31, warpid = tid >> 5;   // 0..15
    const int q = lane & 3, g8 = lane >> 2;
    const int m0 = blockIdx.x * LM;

    // one-time stage trajectories
    for (int i = tid; i < (LM*HLEN*4)/4; i += LTPB)
        ((float4*)trj)[i] = ((const float4*)(traj + (size_t)m0 * (HLEN*4)))[i];
    // x_0 + 1.0 + zeros into H0 cols 512..527
    if (tid < LM) {
        float4 xv = *(const float4*)(traj + (size_t)(m0 + tid) * (HLEN*4));
        uint32_t* dst = (uint32_t*)(smem + OFF_H0) + tid*HRW + 256;
        dst[0] = bf2(xv.x, xv.y); dst[1] = bf2(xv.z, xv.w); dst[2] = bf2(1.0f, 0.0f);
        dst[3] = 0; dst[4] = 0; dst[5] = 0; dst[6] = 0; dst[7] = 0;
    }
    __syncthreads();

    const uint2* __restrict__ Wf64 = (const uint2*)g_Wf;
    // ldmatrix per-lane address component: row (lane&15), +4 words for lanes>=16
    const uint32_t lmoff = (((lane & 15) * HRW + ((lane >> 4) << 2)) << 2);
    const uint32_t h0b = smem_u32(smem + OFF_H0) + lmoff;
    const uint32_t h1b = smem_u32(smem + OFF_H1) + lmoff;

    for (int t = 0; t < HLEN; ++t) {
        const uint32_t hcur_b = (t & 1) ? h1b : h0b;
        char*          hnb  = smem + ((t & 1) ? OFF_H0 : OFF_H1);
        __nv_bfloat16* hnxt = (__nv_bfloat16*)hnb;

        for (int ncp = 0; ncp < 4; ++ncp) {
            float acc[4][4][4];
            #pragma unroll
            for (int mt = 0; mt < 4; ++mt)
                #pragma unroll
                for (int nt = 0; nt < 4; ++nt)
                    #pragma unroll
                    for (int c = 0; c < 4; ++c) acc[mt][nt][c] = 0.0f;

            const int ks0 = (t == 0) ? (KSLN - 1) : 0;
            const uint2* Bp = Wf64 + (((size_t)ncp*KSLN*16 + warpid)*4)*32 + lane;
            uint2 bc[4], bn[4];
            #pragma unroll
            for (int nt = 0; nt < 4; ++nt) bc[nt] = Bp[(size_t)ks0*2048 + nt*32];

            for (int ksl = ks0; ksl < KSLN; ++ksl) {
                if (ksl < KSLN - 1) {
                    const uint2* Bn = Bp + (size_t)(ksl + 1) * 2048;
                    #pragma unroll
                    for (int nt = 0; nt < 4; ++nt) bn[nt] = Bn[nt*32];
                }
                uint32_t a[4][4];
                const uint32_t aaddr = hcur_b + ksl*32;
                #pragma unroll
                for (int mt = 0; mt < 4; ++mt)
                    LDSM4(a[mt], aaddr + mt*(16*HRW*4));
                #pragma unroll
                for (int nt = 0; nt < 4; ++nt) {
                    #pragma unroll
                    for (int mt = 0; mt < 4; ++mt)
                        MMA_BF16(acc[mt][nt], a[mt], bc[nt].x, bc[nt].y);
                }
                #pragma unroll
                for (int nt = 0; nt < 4; ++nt) bc[nt] = bn[nt];
            }

            // ---- epilogue ----
            #pragma unroll
            for (int j2 = 0; j2 < 2; ++j2) {
                const int kg = ncp*128 + warpid*8 + j2*4 + q;
                #pragma unroll
                for (int mt = 0; mt < 4; ++mt) {
                    #pragma unroll
                    for (int half = 0; half < 2; ++half) {
                        const int row = mt*16 + g8 + half*8;
                        const float gi = acc[mt][j2  ][half*2  ];
                        const float gf = acc[mt][j2  ][half*2+1];
                        const float gg = acc[mt][j2+2][half*2  ];
                        const float go = acc[mt][j2+2][half*2+1];
                        const int cidx = ((ncp*2 + j2)*8 + mt*2 + half)*LTPB + tid;
                        float cp = (t > 0) ? __half2float(c_s[cidx]) : 0.0f;
                        float cn = sig_ap(gf) * cp + sig_ap(gi) * tanh_ap(gg);
                        c_s[cidx] = __float2half(cn);
                        float hn = sig_ap(go) * tanh_ap(cn);
                        hnxt[row*536 + kg] = __float2bfloat16_rn(hn);
                        if (t == HLEN - 1) g_hn[(size_t)(m0 + row)*HIDN + kg] = hn;
                    }
                }
            }
        }

        // stage x_{t+1} + 1.0 into hnxt cols 512..527
        if (t < HLEN - 1 && tid < LM) {
            float4 xv = *(const float4*)(trj + tid*60 + (t+1)*4);
            uint32_t* dst = (uint32_t*)hnb + tid*HRW + 256;
            dst[0] = bf2(xv.x, xv.y); dst[1] = bf2(xv.z, xv.w); dst[2] = bf2(1.0f, 0.0f);
            dst[3] = 0; dst[4] = 0; dst[5] = 0; dst[6] = 0; dst[7] = 0;
        }
        __syncthreads();
    }
}

// ---------------------------------------------------------------------------
__global__ void alpha_kernel(const float* __restrict__ ego_speed, const float* __restrict__ gps_conf,
                             const float* __restrict__ W_g1, const float* __restrict__ b_g1,
                             const float* __restrict__ W_g2, const float* __restrict__ b_g2)
{
    int b = threadIdx.x;
    if (b < 32) {
        float s = ego_speed[b], c = gps_conf[b];
        float acc = b_g2[0];
        #pragma unroll
        for (int h = 0; h < 16; ++h) {
            float t = W_g1[2*h]*s + W_g1[2*h+1]*c + b_g1[h];
            acc += W_g2[h] * fmaxf(t, 0.0f);
        }
        g_alpha[b] = 1.0f / (1.0f + expf(-acc));
    }
}

// ---------------------------------------------------------------------------
// fuse via mma.sync bf16 + ldmatrix A loads.
// ---------------------------------------------------------------------------
__global__ __launch_bounds__(FTPB, 1)
void fuse_mma_kernel(const float* __restrict__ tokens, const float* __restrict__ habs,
                     const float* __restrict__ W_abs,
                     const float* __restrict__ gamma, const float* __restrict__ beta,
                     float* __restrict__ out)
{
    extern __shared__ char smem[];
    uint32_t* hs   = (uint32_t*)(smem + FO_HS);
    float*    hb   = (float*)   (smem + FO_HB);
    float*    redS = (float*)   (smem + FO_RS);
    float*    redQ = (float*)   (smem + FO_RQ);
    float*    mu_s = (float*)   (smem + FO_MU);
    float*    rs_s = (float*)   (smem + FO_RV);

    const int tid = threadIdx.x;
    const int lane = tid & 31, warpid = tid >> 5;
    const int q = lane & 3, g8 = lane >> 2;
    const int m0 = blockIdx.x * FM;

    for (int i = tid; i < FM*256; i += FTPB) {
        int row = i >> 8, kw = i & 255;
        float2 v = ((const float2*)(g_hn + (size_t)(m0 + row)*HIDN))[kw];
        hs[row*FHW + kw] = bf2(v.x, v.y);
    }
    for (int i = tid; i < FM*2; i += FTPB) hb[i] = habs[(size_t)m0*2 + i];
    __syncthreads();

    const float al = g_alpha[m0 >> 9], ali = 1.0f - al;
    const uint2* __restrict__ Wr64 = (const uint2*)g_Wrf;
    const uint32_t hs_b = smem_u32(smem + FO_HS) + (((lane & 15) * FHW + ((lane >> 4) << 2)) << 2);

    float rsum[8], rq[8];
    #pragma unroll
    for (int s = 0; s < 8; ++s) { rsum[s] = 0.0f; rq[s] = 0.0f; }

    #pragma unroll
    for (int ch = 0; ch < 2; ++ch) {
        float acc[4][8][4];
        #pragma unroll
        for (int mt = 0; mt < 4; ++mt)
            #pragma unroll
            for (int nt = 0; nt < 8; ++nt)
                #pragma unroll
                for (int c = 0; c < 4; ++c) acc[mt][nt][c] = 0.0f;

        const uint2* Bp = Wr64 + ((size_t)(warpid*2 + ch)*32*8)*32 + lane;
        uint2 bc[8], bn[8];
        #pragma unroll
        for (int nt = 0; nt < 8; ++nt) bc[nt] = Bp[nt*32];

        for (int ksl = 0; ksl < 32; ++ksl) {
            if (ksl < 31) {
                const uint2* Bn = Bp + (size_t)(ksl + 1) * 256;
                #pragma unroll
                for (int nt = 0; nt < 8; ++nt) bn[nt] = Bn[nt*32];
            }
            uint32_t a[4][4];
            const uint32_t aaddr = hs_b + ksl*32;
            #pragma unroll
            for (int mt = 0; mt < 4; ++mt)
                LDSM4(a[mt], aaddr + mt*(16*FHW*4));
            #pragma unroll
            for (int nt = 0; nt < 8; ++nt) {
                #pragma unroll
                for (int mt = 0; mt < 4; ++mt)
                    MMA_BF16(acc[mt][nt], a[mt], bc[nt].x, bc[nt].y);
            }
            #pragma unroll
            for (int nt = 0; nt < 8; ++nt) bc[nt] = bn[nt];
        }

        #pragma unroll
        for (int mt = 0; mt < 4; ++mt) {
            #pragma unroll
            for (int half = 0; half < 2; ++half) {
                const int row = mt*16 + g8 + half*8;
                const int R   = m0 + row;
                const float h0 = hb[row*2], h1 = hb[row*2+1];
                const int slot = mt*2 + half;
                #pragma unroll
                for (int nt = 0; nt < 8; ++nt) {
                    const int col = warpid*128 + ch*64 + nt*8 + q*2;
                    float2 tk  = *(const float2*)(tokens + (size_t)R*DIM + col);
                    float2 wa0 = ((const float2*)W_abs)[col];
                    float2 wa1 = ((const float2*)W_abs)[col+1];
                    float x0 = tk.x + al*acc[mt][nt][half*2  ] + ali*(h0*wa0.x + h1*wa0.y);
                    float x1 = tk.y + al*acc[mt][nt][half*2+1] + ali*(h0*wa1.x + h1*wa1.y);
                    *(float2*)(out + (size_t)R*DIM + col) = make_float2(x0, x1);
                    rsum[slot] += x0 + x1;
                    rq[slot]   += x0*x0 + x1*x1;
                }
            }
        }
    }

    __syncthreads();
    #pragma unroll
    for (int mt = 0; mt < 4; ++mt)
        #pragma unroll
        for (int half = 0; half < 2; ++half) {
            const int row = mt*16 + g8 + half*8;
            redS[row*32 + warpid*4 + q] = rsum[mt*2 + half];
            redQ[row*32 + warpid*4 + q] = rq[mt*2 + half];
        }
    __syncthreads();
    if (tid < FM) {
        float s = 0.0f, qq = 0.0f;
        #pragma unroll
        for (int i = 0; i < 32; ++i) { s += redS[tid*32 + i]; qq += redQ[tid*32 + i]; }
        float mu = s * (1.0f/DIM);
        float var = qq * (1.0f/DIM) - mu*mu;
        mu_s[tid] = mu; rs_s[tid] = rsqrtf(var + 1e-5f);
    }
    __syncthreads();

    for (int i = tid; i < (FM*DIM)/4; i += FTPB) {
        int mm = i >> 8, j4 = i & 255;
        float4 v = ((float4*)(out + (size_t)(m0 + mm)*DIM))[j4];
        float4 g = ((const float4*)gamma)[j4];
        float4 b = ((const float4*)beta)[j4];
        float mu = mu_s[mm], rr = rs_s[mm];
        v.x = (v.x - mu)*rr*g.x + b.x;
        v.y = (v.y - mu)*rr*g.y + b.y;
        v.z = (v.z - mu)*rr*g.z + b.z;
        v.w = (v.w - mu)*rr*g.w + b.w;
        ((float4*)(out + (size_t)(m0 + mm)*DIM))[j4] = v;
    }
}

// ---------------------------------------------------------------------------
extern "C" void kernel_launch(void* const* d_in, const int* in_sizes, int n_in,
                              void* d_out, int out_size)
{
    const float* tokens = (const float*)d_in[0];
    const float* traj   = (const float*)d_in[1];
    const float* habs   = (const float*)d_in[2];
    const float* espeed = (const float*)d_in[3];
    const float* gconf  = (const float*)d_in[4];
    const float* W_ih   = (const float*)d_in[5];
    const float* W_hh   = (const float*)d_in[6];
    const float* b_ih   = (const float*)d_in[7];
    const float* b_hh   = (const float*)d_in[8];
    const float* W_rel  = (const float*)d_in[9];
    const float* W_abs  = (const float*)d_in[10];
    const float* W_g1   = (const float*)d_in[11];
    const float* b_g1   = (const float*)d_in[12];
    const float* W_g2   = (const float*)d_in[13];
    const float* b_g2   = (const float*)d_in[14];
    const float* gamma  = (const float*)d_in[15];
    const float* beta   = (const float*)d_in[16];
    float* out = (float*)d_out;

    cudaFuncSetAttribute(lstm_mma_kernel, cudaFuncAttributeMaxDynamicSharedMemorySize, LSMEM);
    cudaFuncSetAttribute(fuse_mma_kernel, cudaFuncAttributeMaxDynamicSharedMemorySize, FSMEM);

    reorder_kernel<<<G4 + DIM, 128>>>(W_hh, W_ih, b_ih, b_hh, W_rel);
    lstm_mma_kernel<<<NCTA, LTPB, LSMEM>>>(traj);
    alpha_kernel<<<1, 32>>>(espeed, gconf, W_g1, b_g1, W_g2, b_g2);
    fuse_mma_kernel<<<BN/FM, FTPB, FSMEM>>>(tokens, habs, W_abs, gamma, beta, out);
}

// round 13
// speedup vs baseline: 2.5688x; 1.0318x over previous
#include <cuda_runtime.h>
#include <cuda_bf16.h>
#include <cuda_fp16.h>
#include <math.h>
#include <stdint.h>
#include <string.h>

// ---------------- problem constants ----------------
#define BN      16384
#define HIDN    512
#define G4      2048
#define HLEN    15
#define DIM     1024

// ---------------- LSTM mma bf16 config ----------------
#define LTPB    512            // 16 warps (4 per SMSP)
#define NCTA1   148            // wave-1 CTAs: 64 rows
#define NCTA2   144            // wave-2 CTAs: 48 rows   (148*64+144*48 = 16384)
#define KSLN    33             // K slices: 512 h + 16 (x,1,pad)
#define HRW     268            // h row stride in u32 words (=536 bf16); conflict-free

// LSTM smem layout (bytes) — sized for 64 rows
#define OFF_H0   0              // 64*536*2 = 68608
#define OFF_H1   68608
#define OFF_C    137216         // c fp16 [64 slots][512 tid] = 65536
#define OFF_TRJ  202752         // 64*60*4 = 15360
#define LSMEM    218112

// fuse_mma smem layout (bytes) — unchanged
#define FTPB     256
#define FHW      260
#define FO_HS    0
#define FO_HB    66560
#define FO_RS    67072
#define FO_RQ    75264
#define FO_MU    83456
#define FO_RV    83712
#define FSMEM    83968
#define FM       64

// ---------------- device scratch ----------------
__device__ float    g_hn [BN * HIDN];              // final hidden (fp32)
__device__ float    g_alpha[32];
__device__ uint32_t g_Wf [4*KSLN*16*4*32*2];       // W_hh+W_ih+bias bf16x2 fragment order
__device__ uint32_t g_Wrf[DIM * HIDN / 2];         // W_rel bf16x2 fragment order

// ---------------- helpers ----------------
__device__ __forceinline__ float tanh_ap(float x){
    float y; asm("tanh.approx.f32 %0, %1;" : "=f"(y) : "f"(x)); return y;
}
__device__ __forceinline__ float sig_ap(float x){
    return fmaf(tanh_ap(0.5f*x), 0.5f, 0.5f);
}
__device__ __forceinline__ uint32_t smem_u32(const void* p){
    uint32_t a; asm("{ .reg .u64 t; cvta.to.shared.u64 t, %1; cvt.u32.u64 %0, t; }":"=r"(a):"l"(p)); return a;
}
#define MMA_BF16(c, a, b0, b1) \
    asm volatile("mma.sync.aligned.m16n8k16.row.col.f32.bf16.bf16.f32 " \
        "{%0,%1,%2,%3}, {%4,%5,%6,%7}, {%8,%9}, {%0,%1,%2,%3};" \
        : "+f"((c)[0]), "+f"((c)[1]), "+f"((c)[2]), "+f"((c)[3]) \
        : "r"((a)[0]), "r"((a)[1]), "r"((a)[2]), "r"((a)[3]), "r"(b0), "r"(b1))
#define LDSM4(r, addr) \
    asm volatile("ldmatrix.sync.aligned.m8n8.x4.shared.b16 {%0,%1,%2,%3}, [%4];" \
        : "=r"((r)[0]), "=r"((r)[1]), "=r"((r)[2]), "=r"((r)[3]) : "r"(addr))

__device__ __forceinline__ uint32_t bf2(float a, float b){
    __nv_bfloat162 p = __floats2bfloat162_rn(a, b);
    uint32_t u; memcpy(&u, &p, 4); return u;
}

// ---------------------------------------------------------------------------
// reorder (unchanged — proven).
// ---------------------------------------------------------------------------
__global__ void reorder_kernel(const float* __restrict__ Whh, const float* __restrict__ Wih,
                               const float* __restrict__ bih, const float* __restrict__ bhh,
                               const float* __restrict__ Wrel)
{
    if (blockIdx.x < G4) {
        int n = blockIdx.x;
        int pass = n >> 9, w16 = (n >> 5) & 15, cw = n & 31;
        int j = cw >> 3, qq = (cw >> 1) & 3, r = cw & 1;
        int gate, ul;
        if (j < 2) { ul = j*4 + qq;     gate = r;     }
        else       { ul = (j-2)*4 + qq; gate = 2 + r; }
        int unit = pass*128 + w16*8 + ul;
        int srow = gate * HIDN + unit;

        const float* src = Whh + (size_t)srow * HIDN;
        float bsum = bih[srow] + bhh[srow];
        int colin = cw & 7;

        for (int k2 = threadIdx.x; k2 < (KSLN*16)/2; k2 += blockDim.x) {
            int k = k2 * 2;
            int ksl = k >> 4, kin = k & 15;
            float v0, v1;
            if (ksl < 32) { v0 = src[k]; v1 = src[k+1]; }
            else {
                v0 = (kin < 4) ? Wih[srow*4 + kin] : (kin == 4 ? bsum : 0.0f);
                v1 = (kin + 1 < 4) ? Wih[srow*4 + kin + 1] : 0.0f;
            }
            int jj = kin >> 3, qk = (kin >> 1) & 3;
            int lane = colin*4 + qk;
            size_t idx = ((((((size_t)pass*KSLN + ksl)*16 + w16)*4 + j)*32 + lane)*2 + jj);
            g_Wf[idx] = bf2(v0, v1);
        }
    } else {
        int n = blockIdx.x - G4;
        const float* src = Wrel + (size_t)n * HIDN;
        int w = n >> 7, ch = (n >> 6) & 1, nt = (n >> 3) & 7, g8 = n & 7;
        for (int k2 = threadIdx.x; k2 < HIDN/2; k2 += blockDim.x) {
            int k = k2 * 2;
            int ksl = k >> 4, kin = k & 15;
            int jj = kin >> 3, qk = (kin >> 1) & 3;
            int lane = g8*4 + qk;
            size_t idx = ((((((size_t)(w*2 + ch))*32 + ksl)*8 + nt)*32 + lane)*2 + jj);
            g_Wrf[idx] = bf2(src[k], src[k+1]);
        }
    }
}

// ---------------------------------------------------------------------------
// LSTM body, templated on the number of 16-row m-tiles (4 -> 64 rows, 3 -> 48).
// ---------------------------------------------------------------------------
template<int MTN>
__device__ __forceinline__ void lstm_body(const float* __restrict__ traj, int m0)
{
    extern __shared__ char smem[];
    float*  trj = (float*) (smem + OFF_TRJ);
    __half* c_s = (__half*)(smem + OFF_C);
    const int ROWS = MTN * 16;

    const int tid = threadIdx.x;
    const int lane = tid & 31, warpid = tid >> 5;
    const int q = lane & 3, g8 = lane >> 2;

    for (int i = tid; i < (ROWS*HLEN*4)/4; i += LTPB)
        ((float4*)trj)[i] = ((const float4*)(traj + (size_t)m0 * (HLEN*4)))[i];
    if (tid < ROWS) {
        float4 xv = *(const float4*)(traj + (size_t)(m0 + tid) * (HLEN*4));
        uint32_t* dst = (uint32_t*)(smem + OFF_H0) + tid*HRW + 256;
        dst[0] = bf2(xv.x, xv.y); dst[1] = bf2(xv.z, xv.w); dst[2] = bf2(1.0f, 0.0f);
        dst[3] = 0; dst[4] = 0; dst[5] = 0; dst[6] = 0; dst[7] = 0;
    }
    __syncthreads();

    const uint2* __restrict__ Wf64 = (const uint2*)g_Wf;
    const uint32_t lmoff = (((lane & 15) * HRW + ((lane >> 4) << 2)) << 2);
    const uint32_t h0b = smem_u32(smem + OFF_H0) + lmoff;
    const uint32_t h1b = smem_u32(smem + OFF_H1) + lmoff;

    for (int t = 0; t < HLEN; ++t) {
        const uint32_t hcur_b = (t & 1) ? h1b : h0b;
        char*          hnb  = smem + ((t & 1) ? OFF_H0 : OFF_H1);
        __nv_bfloat16* hnxt = (__nv_bfloat16*)hnb;

        for (int ncp = 0; ncp < 4; ++ncp) {
            float acc[MTN][4][4];
            #pragma unroll
            for (int mt = 0; mt < MTN; ++mt)
                #pragma unroll
                for (int nt = 0; nt < 4; ++nt)
                    #pragma unroll
                    for (int c = 0; c < 4; ++c) acc[mt][nt][c] = 0.0f;

            const int ks0 = (t == 0) ? (KSLN - 1) : 0;
            const uint2* Bp = Wf64 + (((size_t)ncp*KSLN*16 + warpid)*4)*32 + lane;
            uint2 bc[4], bn[4];
            #pragma unroll
            for (int nt = 0; nt < 4; ++nt) bc[nt] = Bp[(size_t)ks0*2048 + nt*32];

            for (int ksl = ks0; ksl < KSLN; ++ksl) {
                if (ksl < KSLN - 1) {
                    const uint2* Bn = Bp + (size_t)(ksl + 1) * 2048;
                    #pragma unroll
                    for (int nt = 0; nt < 4; ++nt) bn[nt] = Bn[nt*32];
                }
                uint32_t a[MTN][4];
                const uint32_t aaddr = hcur_b + ksl*32;
                #pragma unroll
                for (int mt = 0; mt < MTN; ++mt)
                    LDSM4(a[mt], aaddr + mt*(16*HRW*4));
                #pragma unroll
                for (int nt = 0; nt < 4; ++nt) {
                    #pragma unroll
                    for (int mt = 0; mt < MTN; ++mt)
                        MMA_BF16(acc[mt][nt], a[mt], bc[nt].x, bc[nt].y);
                }
                #pragma unroll
                for (int nt = 0; nt < 4; ++nt) bc[nt] = bn[nt];
            }

            // ---- epilogue ----
            #pragma unroll
            for (int j2 = 0; j2 < 2; ++j2) {
                const int kg = ncp*128 + warpid*8 + j2*4 + q;
                #pragma unroll
                for (int mt = 0; mt < MTN; ++mt) {
                    #pragma unroll
                    for (int half = 0; half < 2; ++half) {
                        const int row = mt*16 + g8 + half*8;
                        const float gi = acc[mt][j2  ][half*2  ];
                        const float gf = acc[mt][j2  ][half*2+1];
                        const float gg = acc[mt][j2+2][half*2  ];
                        const float go = acc[mt][j2+2][half*2+1];
                        const int cidx = ((ncp*2 + j2)*8 + mt*2 + half)*LTPB + tid;
                        float cp = (t > 0) ? __half2float(c_s[cidx]) : 0.0f;
                        float cn = sig_ap(gf) * cp + sig_ap(gi) * tanh_ap(gg);
                        c_s[cidx] = __float2half(cn);
                        float hn = sig_ap(go) * tanh_ap(cn);
                        hnxt[row*536 + kg] = __float2bfloat16_rn(hn);
                        if (t == HLEN - 1) g_hn[(size_t)(m0 + row)*HIDN + kg] = hn;
                    }
                }
            }
        }

        if (t < HLEN - 1 && tid < ROWS) {
            float4 xv = *(const float4*)(trj + tid*60 + (t+1)*4);
            uint32_t* dst = (uint32_t*)hnb + tid*HRW + 256;
            dst[0] = bf2(xv.x, xv.y); dst[1] = bf2(xv.z, xv.w); dst[2] = bf2(1.0f, 0.0f);
            dst[3] = 0; dst[4] = 0; dst[5] = 0; dst[6] = 0; dst[7] = 0;
        }
        __syncthreads();
    }
}

// Mixed-size grid: CTAs 0..147 handle 64 rows, 148..291 handle 48 rows.
__global__ __launch_bounds__(LTPB, 1)
void lstm_mma_kernel(const float* __restrict__ traj)
{
    const int bid = blockIdx.x;
    if (bid < NCTA1) lstm_body<4>(traj, bid * 64);
    else             lstm_body<3>(traj, NCTA1*64 + (bid - NCTA1) * 48);
}

// ---------------------------------------------------------------------------
__global__ void alpha_kernel(const float* __restrict__ ego_speed, const float* __restrict__ gps_conf,
                             const float* __restrict__ W_g1, const float* __restrict__ b_g1,
                             const float* __restrict__ W_g2, const float* __restrict__ b_g2)
{
    int b = threadIdx.x;
    if (b < 32) {
        float s = ego_speed[b], c = gps_conf[b];
        float acc = b_g2[0];
        #pragma unroll
        for (int h = 0; h < 16; ++h) {
            float t = W_g1[2*h]*s + W_g1[2*h+1]*c + b_g1[h];
            acc += W_g2[h] * fmaxf(t, 0.0f);
        }
        g_alpha[b] = 1.0f / (1.0f + expf(-acc));
    }
}

// ---------------------------------------------------------------------------
// fuse via mma.sync bf16 + ldmatrix A loads (unchanged — proven at 117 us)
// ---------------------------------------------------------------------------
__global__ __launch_bounds__(FTPB, 1)
void fuse_mma_kernel(const float* __restrict__ tokens, const float* __restrict__ habs,
                     const float* __restrict__ W_abs,
                     const float* __restrict__ gamma, const float* __restrict__ beta,
                     float* __restrict__ out)
{
    extern __shared__ char smem[];
    uint32_t* hs   = (uint32_t*)(smem + FO_HS);
    float*    hb   = (float*)   (smem + FO_HB);
    float*    redS = (float*)   (smem + FO_RS);
    float*    redQ = (float*)   (smem + FO_RQ);
    float*    mu_s = (float*)   (smem + FO_MU);
    float*    rs_s = (float*)   (smem + FO_RV);

    const int tid = threadIdx.x;
    const int lane = tid & 31, warpid = tid >> 5;
    const int q = lane & 3, g8 = lane >> 2;
    const int m0 = blockIdx.x * FM;

    for (int i = tid; i < FM*256; i += FTPB) {
        int row = i >> 8, kw = i & 255;
        float2 v = ((const float2*)(g_hn + (size_t)(m0 + row)*HIDN))[kw];
        hs[row*FHW + kw] = bf2(v.x, v.y);
    }
    for (int i = tid; i < FM*2; i += FTPB) hb[i] = habs[(size_t)m0*2 + i];
    __syncthreads();

    const float al = g_alpha[m0 >> 9], ali = 1.0f - al;
    const uint2* __restrict__ Wr64 = (const uint2*)g_Wrf;
    const uint32_t hs_b = smem_u32(smem + FO_HS) + (((lane & 15) * FHW + ((lane >> 4) << 2)) << 2);

    float rsum[8], rq[8];
    #pragma unroll
    for (int s = 0; s < 8; ++s) { rsum[s] = 0.0f; rq[s] = 0.0f; }

    #pragma unroll
    for (int ch = 0; ch < 2; ++ch) {
        float acc[4][8][4];
        #pragma unroll
        for (int mt = 0; mt < 4; ++mt)
            #pragma unroll
            for (int nt = 0; nt < 8; ++nt)
                #pragma unroll
                for (int c = 0; c < 4; ++c) acc[mt][nt][c] = 0.0f;

        const uint2* Bp = Wr64 + ((size_t)(warpid*2 + ch)*32*8)*32 + lane;
        uint2 bc[8], bn[8];
        #pragma unroll
        for (int nt = 0; nt < 8; ++nt) bc[nt] = Bp[nt*32];

        for (int ksl = 0; ksl < 32; ++ksl) {
            if (ksl < 31) {
                const uint2* Bn = Bp + (size_t)(ksl + 1) * 256;
                #pragma unroll
                for (int nt = 0; nt < 8; ++nt) bn[nt] = Bn[nt*32];
            }
            uint32_t a[4][4];
            const uint32_t aaddr = hs_b + ksl*32;
            #pragma unroll
            for (int mt = 0; mt < 4; ++mt)
                LDSM4(a[mt], aaddr + mt*(16*FHW*4));
            #pragma unroll
            for (int nt = 0; nt < 8; ++nt) {
                #pragma unroll
                for (int mt = 0; mt < 4; ++mt)
                    MMA_BF16(acc[mt][nt], a[mt], bc[nt].x, bc[nt].y);
            }
            #pragma unroll
            for (int nt = 0; nt < 8; ++nt) bc[nt] = bn[nt];
        }

        #pragma unroll
        for (int mt = 0; mt < 4; ++mt) {
            #pragma unroll
            for (int half = 0; half < 2; ++half) {
                const int row = mt*16 + g8 + half*8;
                const int R   = m0 + row;
                const float h0 = hb[row*2], h1 = hb[row*2+1];
                const int slot = mt*2 + half;
                #pragma unroll
                for (int nt = 0; nt < 8; ++nt) {
                    const int col = warpid*128 + ch*64 + nt*8 + q*2;
                    float2 tk  = *(const float2*)(tokens + (size_t)R*DIM + col);
                    float2 wa0 = ((const float2*)W_abs)[col];
                    float2 wa1 = ((const float2*)W_abs)[col+1];
                    float x0 = tk.x + al*acc[mt][nt][half*2  ] + ali*(h0*wa0.x + h1*wa0.y);
                    float x1 = tk.y + al*acc[mt][nt][half*2+1] + ali*(h0*wa1.x + h1*wa1.y);
                    *(float2*)(out + (size_t)R*DIM + col) = make_float2(x0, x1);
                    rsum[slot] += x0 + x1;
                    rq[slot]   += x0*x0 + x1*x1;
                }
            }
        }
    }

    __syncthreads();
    #pragma unroll
    for (int mt = 0; mt < 4; ++mt)
        #pragma unroll
        for (int half = 0; half < 2; ++half) {
            const int row = mt*16 + g8 + half*8;
            redS[row*32 + warpid*4 + q] = rsum[mt*2 + half];
            redQ[row*32 + warpid*4 + q] = rq[mt*2 + half];
        }
    __syncthreads();
    if (tid < FM) {
        float s = 0.0f, qq = 0.0f;
        #pragma unroll
        for (int i = 0; i < 32; ++i) { s += redS[tid*32 + i]; qq += redQ[tid*32 + i]; }
        float mu = s * (1.0f/DIM);
        float var = qq * (1.0f/DIM) - mu*mu;
        mu_s[tid] = mu; rs_s[tid] = rsqrtf(var + 1e-5f);
    }
    __syncthreads();

    for (int i = tid; i < (FM*DIM)/4; i += FTPB) {
        int mm = i >> 8, j4 = i & 255;
        float4 v = ((float4*)(out + (size_t)(m0 + mm)*DIM))[j4];
        float4 g = ((const float4*)gamma)[j4];
        float4 b = ((const float4*)beta)[j4];
        float mu = mu_s[mm], rr = rs_s[mm];
        v.x = (v.x - mu)*rr*g.x + b.x;
        v.y = (v.y - mu)*rr*g.y + b.y;
        v.z = (v.z - mu)*rr*g.z + b.z;
        v.w = (v.w - mu)*rr*g.w + b.w;
        ((float4*)(out + (size_t)(m0 + mm)*DIM))[j4] = v;
    }
}

// ---------------------------------------------------------------------------
extern "C" void kernel_launch(void* const* d_in, const int* in_sizes, int n_in,
                              void* d_out, int out_size)
{
    const float* tokens = (const float*)d_in[0];
    const float* traj   = (const float*)d_in[1];
    const float* habs   = (const float*)d_in[2];
    const float* espeed = (const float*)d_in[3];
    const float* gconf  = (const float*)d_in[4];
    const float* W_ih   = (const float*)d_in[5];
    const float* W_hh   = (const float*)d_in[6];
    const float* b_ih   = (const float*)d_in[7];
    const float* b_hh   = (const float*)d_in[8];
    const float* W_rel  = (const float*)d_in[9];
    const float* W_abs  = (const float*)d_in[10];
    const float* W_g1   = (const float*)d_in[11];
    const float* b_g1   = (const float*)d_in[12];
    const float* W_g2   = (const float*)d_in[13];
    const float* b_g2   = (const float*)d_in[14];
    const float* gamma  = (const float*)d_in[15];
    const float* beta   = (const float*)d_in[16];
    float* out = (float*)d_out;

    cudaFuncSetAttribute(lstm_mma_kernel, cudaFuncAttributeMaxDynamicSharedMemorySize, LSMEM);
    cudaFuncSetAttribute(fuse_mma_kernel, cudaFuncAttributeMaxDynamicSharedMemorySize, FSMEM);

    reorder_kernel<<<G4 + DIM, 128>>>(W_hh, W_ih, b_ih, b_hh, W_rel);
    lstm_mma_kernel<<<NCTA1 + NCTA2, LTPB, LSMEM>>>(traj);
    alpha_kernel<<<1, 32>>>(espeed, gconf, W_g1, b_g1, W_g2, b_g2);
    fuse_mma_kernel<<<BN/FM, FTPB, FSMEM>>>(tokens, habs, W_abs, gamma, beta, out);
}

// round 14
// speedup vs baseline: 2.8673x; 1.1162x over previous
#include <cuda_runtime.h>
#include <cuda_bf16.h>
#include <cuda_fp16.h>
#include <math.h>
#include <stdint.h>
#include <string.h>

// ---------------- problem constants ----------------
#define BN      16384
#define HIDN    512
#define G4      2048
#define HLEN    15
#define DIM     1024

// ---------------- LSTM mma bf16 config ----------------
#define LTPB    512            // 16 warps (4 per SMSP)
#define NCTA1   148            // wave-1 CTAs: 64 rows
#define NCTA2   144            // wave-2 CTAs: 48 rows   (148*64+144*48 = 16384)
#define KSLN    33             // K slices: 512 h + 16 (x,1,pad)
#define HRW     268            // h row stride in u32 words (=536 bf16); conflict-free

// smem layout (bytes) — sized for 64 rows
#define OFF_H0   0              // 64*536*2 = 68608
#define OFF_H1   68608
#define OFF_C    137216         // c fp16 [64 slots][512 tid] = 65536 ; reused as LN scratch in tail
#define OFF_TRJ  202752         // 64*60*4 = 15360
#define OFF_ALF  218112         // 32 f32 alphas
#define LSMEM    218240

// ---------------- device scratch ----------------
__device__ uint32_t g_Wf [4*KSLN*16*4*32*2];       // W_hh+W_ih+bias bf16x2 fragment order
__device__ uint32_t g_Wrf[DIM * HIDN / 2];         // W_rel bf16x2 fragment order

// ---------------- helpers ----------------
__device__ __forceinline__ float tanh_ap(float x){
    float y; asm("tanh.approx.f32 %0, %1;" : "=f"(y) : "f"(x)); return y;
}
__device__ __forceinline__ float sig_ap(float x){
    return fmaf(tanh_ap(0.5f*x), 0.5f, 0.5f);
}
__device__ __forceinline__ uint32_t smem_u32(const void* p){
    uint32_t a; asm("{ .reg .u64 t; cvta.to.shared.u64 t, %1; cvt.u32.u64 %0, t; }":"=r"(a):"l"(p)); return a;
}
#define MMA_BF16(c, a, b0, b1) \
    asm volatile("mma.sync.aligned.m16n8k16.row.col.f32.bf16.bf16.f32 " \
        "{%0,%1,%2,%3}, {%4,%5,%6,%7}, {%8,%9}, {%0,%1,%2,%3};" \
        : "+f"((c)[0]), "+f"((c)[1]), "+f"((c)[2]), "+f"((c)[3]) \
        : "r"((a)[0]), "r"((a)[1]), "r"((a)[2]), "r"((a)[3]), "r"(b0), "r"(b1))
#define LDSM4(r, addr) \
    asm volatile("ldmatrix.sync.aligned.m8n8.x4.shared.b16 {%0,%1,%2,%3}, [%4];" \
        : "=r"((r)[0]), "=r"((r)[1]), "=r"((r)[2]), "=r"((r)[3]) : "r"(addr))

__device__ __forceinline__ uint32_t bf2(float a, float b){
    __nv_bfloat162 p = __floats2bfloat162_rn(a, b);
    uint32_t u; memcpy(&u, &p, 4); return u;
}

// ---------------------------------------------------------------------------
// reorder (unchanged — proven).
// ---------------------------------------------------------------------------
__global__ void reorder_kernel(const float* __restrict__ Whh, const float* __restrict__ Wih,
                               const float* __restrict__ bih, const float* __restrict__ bhh,
                               const float* __restrict__ Wrel)
{
    if (blockIdx.x < G4) {
        int n = blockIdx.x;
        int pass = n >> 9, w16 = (n >> 5) & 15, cw = n & 31;
        int j = cw >> 3, qq = (cw >> 1) & 3, r = cw & 1;
        int gate, ul;
        if (j < 2) { ul = j*4 + qq;     gate = r;     }
        else       { ul = (j-2)*4 + qq; gate = 2 + r; }
        int unit = pass*128 + w16*8 + ul;
        int srow = gate * HIDN + unit;

        const float* src = Whh + (size_t)srow * HIDN;
        float bsum = bih[srow] + bhh[srow];
        int colin = cw & 7;

        for (int k2 = threadIdx.x; k2 < (KSLN*16)/2; k2 += blockDim.x) {
            int k = k2 * 2;
            int ksl = k >> 4, kin = k & 15;
            float v0, v1;
            if (ksl < 32) { v0 = src[k]; v1 = src[k+1]; }
            else {
                v0 = (kin < 4) ? Wih[srow*4 + kin] : (kin == 4 ? bsum : 0.0f);
                v1 = (kin + 1 < 4) ? Wih[srow*4 + kin + 1] : 0.0f;
            }
            int jj = kin >> 3, qk = (kin >> 1) & 3;
            int lane = colin*4 + qk;
            size_t idx = ((((((size_t)pass*KSLN + ksl)*16 + w16)*4 + j)*32 + lane)*2 + jj);
            g_Wf[idx] = bf2(v0, v1);
        }
    } else {
        int n = blockIdx.x - G4;
        const float* src = Wrel + (size_t)n * HIDN;
        int w = n >> 7, ch = (n >> 6) & 1, nt = (n >> 3) & 7, g8 = n & 7;
        for (int k2 = threadIdx.x; k2 < HIDN/2; k2 += blockDim.x) {
            int k = k2 * 2;
            int ksl = k >> 4, kin = k & 15;
            int jj = kin >> 3, qk = (kin >> 1) & 3;
            int lane = g8*4 + qk;
            size_t idx = ((((((size_t)(w*2 + ch))*32 + ksl)*8 + nt)*32 + lane)*2 + jj);
            g_Wrf[idx] = bf2(src[k], src[k+1]);
        }
    }
}

// ---------------------------------------------------------------------------
// LSTM + fused projection/LN body, templated on m-tiles (4 -> 64 rows, 3 -> 48).
// ---------------------------------------------------------------------------
template<int MTN>
__device__ __forceinline__ void lstm_fuse_body(
    const float* __restrict__ traj, const float* __restrict__ tokens,
    const float* __restrict__ habs,
    const float* __restrict__ espeed, const float* __restrict__ gconf,
    const float* __restrict__ Wg1, const float* __restrict__ bg1,
    const float* __restrict__ Wg2, const float* __restrict__ bg2,
    const float* __restrict__ W_abs,
    const float* __restrict__ gamma, const float* __restrict__ beta,
    float* __restrict__ out, int m0)
{
    extern __shared__ char smem[];
    float*  trj = (float*) (smem + OFF_TRJ);
    __half* c_s = (__half*)(smem + OFF_C);
    float*  alf = (float*) (smem + OFF_ALF);
    const int ROWS = MTN * 16;

    const int tid = threadIdx.x;
    const int lane = tid & 31, warpid = tid >> 5;
    const int q = lane & 3, g8 = lane >> 2;

    // per-CTA alpha gate for all 32 batches (tiny MLP)
    if (tid < 32) {
        float s = espeed[tid], cg = gconf[tid];
        float acc = bg2[0];
        #pragma unroll
        for (int h = 0; h < 16; ++h) {
            float tv = Wg1[2*h]*s + Wg1[2*h+1]*cg + bg1[h];
            acc += Wg2[h] * fmaxf(tv, 0.0f);
        }
        alf[tid] = 1.0f / (1.0f + expf(-acc));
    }

    for (int i = tid; i < (ROWS*HLEN*4)/4; i += LTPB)
        ((float4*)trj)[i] = ((const float4*)(traj + (size_t)m0 * (HLEN*4)))[i];
    if (tid < ROWS) {
        float4 xv = *(const float4*)(traj + (size_t)(m0 + tid) * (HLEN*4));
        uint32_t* dst = (uint32_t*)(smem + OFF_H0) + tid*HRW + 256;
        dst[0] = bf2(xv.x, xv.y); dst[1] = bf2(xv.z, xv.w); dst[2] = bf2(1.0f, 0.0f);
        dst[3] = 0; dst[4] = 0; dst[5] = 0; dst[6] = 0; dst[7] = 0;
    }
    __syncthreads();

    const uint2* __restrict__ Wf64 = (const uint2*)g_Wf;
    const uint32_t lmoff = (((lane & 15) * HRW + ((lane >> 4) << 2)) << 2);
    const uint32_t h0b = smem_u32(smem + OFF_H0) + lmoff;
    const uint32_t h1b = smem_u32(smem + OFF_H1) + lmoff;

    for (int t = 0; t < HLEN; ++t) {
        const uint32_t hcur_b = (t & 1) ? h1b : h0b;
        char*          hnb  = smem + ((t & 1) ? OFF_H0 : OFF_H1);
        __nv_bfloat16* hnxt = (__nv_bfloat16*)hnb;

        for (int ncp = 0; ncp < 4; ++ncp) {
            float acc[MTN][4][4];
            #pragma unroll
            for (int mt = 0; mt < MTN; ++mt)
                #pragma unroll
                for (int nt = 0; nt < 4; ++nt)
                    #pragma unroll
                    for (int c = 0; c < 4; ++c) acc[mt][nt][c] = 0.0f;

            const int ks0 = (t == 0) ? (KSLN - 1) : 0;
            const uint2* Bp = Wf64 + (((size_t)ncp*KSLN*16 + warpid)*4)*32 + lane;
            uint2 bc[4], bn[4];
            #pragma unroll
            for (int nt = 0; nt < 4; ++nt) bc[nt] = Bp[(size_t)ks0*2048 + nt*32];

            for (int ksl = ks0; ksl < KSLN; ++ksl) {
                if (ksl < KSLN - 1) {
                    const uint2* Bn = Bp + (size_t)(ksl + 1) * 2048;
                    #pragma unroll
                    for (int nt = 0; nt < 4; ++nt) bn[nt] = Bn[nt*32];
                }
                uint32_t a[MTN][4];
                const uint32_t aaddr = hcur_b + ksl*32;
                #pragma unroll
                for (int mt = 0; mt < MTN; ++mt)
                    LDSM4(a[mt], aaddr + mt*(16*HRW*4));
                #pragma unroll
                for (int nt = 0; nt < 4; ++nt) {
                    #pragma unroll
                    for (int mt = 0; mt < MTN; ++mt)
                        MMA_BF16(acc[mt][nt], a[mt], bc[nt].x, bc[nt].y);
                }
                #pragma unroll
                for (int nt = 0; nt < 4; ++nt) bc[nt] = bn[nt];
            }

            // ---- epilogue ----
            #pragma unroll
            for (int j2 = 0; j2 < 2; ++j2) {
                const int kg = ncp*128 + warpid*8 + j2*4 + q;
                #pragma unroll
                for (int mt = 0; mt < MTN; ++mt) {
                    #pragma unroll
                    for (int half = 0; half < 2; ++half) {
                        const int row = mt*16 + g8 + half*8;
                        const float gi = acc[mt][j2  ][half*2  ];
                        const float gf = acc[mt][j2  ][half*2+1];
                        const float gg = acc[mt][j2+2][half*2  ];
                        const float go = acc[mt][j2+2][half*2+1];
                        const int cidx = ((ncp*2 + j2)*8 + mt*2 + half)*LTPB + tid;
                        float cp = (t > 0) ? __half2float(c_s[cidx]) : 0.0f;
                        float cn = sig_ap(gf) * cp + sig_ap(gi) * tanh_ap(gg);
                        c_s[cidx] = __float2half(cn);
                        float hn = sig_ap(go) * tanh_ap(cn);
                        hnxt[row*536 + kg] = __float2bfloat16_rn(hn);
                    }
                }
            }
        }

        if (t < HLEN - 1 && tid < ROWS) {
            float4 xv = *(const float4*)(trj + tid*60 + (t+1)*4);
            uint32_t* dst = (uint32_t*)hnb + tid*HRW + 256;
            dst[0] = bf2(xv.x, xv.y); dst[1] = bf2(xv.z, xv.w); dst[2] = bf2(1.0f, 0.0f);
            dst[3] = 0; dst[4] = 0; dst[5] = 0; dst[6] = 0; dst[7] = 0;
        }
        __syncthreads();
    }

    // =======================================================================
    // fuse tail: out = LN(tokens + al*(h15 @ W_rel^T) + (1-al)*(habs @ W_abs^T))
    // h15 is bf16 in the H1 buffer. LN scratch reuses the c region.
    // 16 warps; warp covers cols warpid*32 (+ch*512), nt=4.
    // =======================================================================
    float* redS = (float*)(smem + OFF_C);      // [64][64]
    float* redQ = redS + 64*64;
    float* mu_s = redQ + 64*64;
    float* rs_s = mu_s + 64;

    const uint2* __restrict__ Wr64 = (const uint2*)g_Wrf;
    float rsum[2*MTN], rq[2*MTN];
    #pragma unroll
    for (int s = 0; s < 2*MTN; ++s) { rsum[s] = 0.0f; rq[s] = 0.0f; }

    #pragma unroll
    for (int ch = 0; ch < 2; ++ch) {
        float acc[MTN][4][4];
        #pragma unroll
        for (int mt = 0; mt < MTN; ++mt)
            #pragma unroll
            for (int nt = 0; nt < 4; ++nt)
                #pragma unroll
                for (int c = 0; c < 4; ++c) acc[mt][nt][c] = 0.0f;

        const uint2* Bp = Wr64 + ((((size_t)(ch*8 + (warpid>>1))*32)*8 + ((warpid&1)*4)))*32 + lane;
        uint2 bc[4], bn[4];
        #pragma unroll
        for (int nt = 0; nt < 4; ++nt) bc[nt] = Bp[nt*32];

        for (int ksl = 0; ksl < 32; ++ksl) {
            if (ksl < 31) {
                const uint2* Bn = Bp + (size_t)(ksl + 1) * 256;
                #pragma unroll
                for (int nt = 0; nt < 4; ++nt) bn[nt] = Bn[nt*32];
            }
            uint32_t a[MTN][4];
            const uint32_t aaddr = h1b + ksl*32;
            #pragma unroll
            for (int mt = 0; mt < MTN; ++mt)
                LDSM4(a[mt], aaddr + mt*(16*HRW*4));
            #pragma unroll
            for (int nt = 0; nt < 4; ++nt) {
                #pragma unroll
                for (int mt = 0; mt < MTN; ++mt)
                    MMA_BF16(acc[mt][nt], a[mt], bc[nt].x, bc[nt].y);
            }
            #pragma unroll
            for (int nt = 0; nt < 4; ++nt) bc[nt] = bn[nt];
        }

        // epilogue: blend + residual, write pre-LN x, accumulate row stats
        #pragma unroll
        for (int mt = 0; mt < MTN; ++mt) {
            #pragma unroll
            for (int half = 0; half < 2; ++half) {
                const int row = mt*16 + g8 + half*8;
                const int R   = m0 + row;
                const float al = alf[R >> 9], ali = 1.0f - al;
                const float2 hv = *(const float2*)(habs + (size_t)R*2);
                const int slot = mt*2 + half;
                #pragma unroll
                for (int nt = 0; nt < 4; ++nt) {
                    const int col = ch*512 + warpid*32 + nt*8 + q*2;
                    float2 tk  = *(const float2*)(tokens + (size_t)R*DIM + col);
                    float2 wa0 = ((const float2*)W_abs)[col];
                    float2 wa1 = ((const float2*)W_abs)[col+1];
                    float x0 = tk.x + al*acc[mt][nt][half*2  ] + ali*(hv.x*wa0.x + hv.y*wa0.y);
                    float x1 = tk.y + al*acc[mt][nt][half*2+1] + ali*(hv.x*wa1.x + hv.y*wa1.y);
                    *(float2*)(out + (size_t)R*DIM + col) = make_float2(x0, x1);
                    rsum[slot] += x0 + x1;
                    rq[slot]   += x0*x0 + x1*x1;
                }
            }
        }
    }

    __syncthreads();   // c region reads done long ago; safe to write redS now
    #pragma unroll
    for (int mt = 0; mt < MTN; ++mt)
        #pragma unroll
        for (int half = 0; half < 2; ++half) {
            const int row = mt*16 + g8 + half*8;
            redS[row*64 + warpid*4 + q] = rsum[mt*2 + half];
            redQ[row*64 + warpid*4 + q] = rq[mt*2 + half];
        }
    __syncthreads();
    if (tid < ROWS) {
        float s = 0.0f, qq = 0.0f;
        #pragma unroll
        for (int i = 0; i < 64; ++i) { s += redS[tid*64 + i]; qq += redQ[tid*64 + i]; }
        float mu = s * (1.0f/DIM);
        float var = qq * (1.0f/DIM) - mu*mu;
        mu_s[tid] = mu; rs_s[tid] = rsqrtf(var + 1e-5f);
    }
    __syncthreads();

    for (int i = tid; i < ROWS*256; i += LTPB) {
        int mm = i >> 8, j4 = i & 255;
        float4 v = ((float4*)(out + (size_t)(m0 + mm)*DIM))[j4];
        float4 g = ((const float4*)gamma)[j4];
        float4 b = ((const float4*)beta)[j4];
        float mu = mu_s[mm], rr = rs_s[mm];
        v.x = (v.x - mu)*rr*g.x + b.x;
        v.y = (v.y - mu)*rr*g.y + b.y;
        v.z = (v.z - mu)*rr*g.z + b.z;
        v.w = (v.w - mu)*rr*g.w + b.w;
        ((float4*)(out + (size_t)(m0 + mm)*DIM))[j4] = v;
    }
}

// Mixed-size grid: CTAs 0..147 handle 64 rows, 148..291 handle 48 rows.
__global__ __launch_bounds__(LTPB, 1)
void lstm_fuse_kernel(const float* __restrict__ traj, const float* __restrict__ tokens,
                      const float* __restrict__ habs,
                      const float* __restrict__ espeed, const float* __restrict__ gconf,
                      const float* __restrict__ Wg1, const float* __restrict__ bg1,
                      const float* __restrict__ Wg2, const float* __restrict__ bg2,
                      const float* __restrict__ W_abs,
                      const float* __restrict__ gamma, const float* __restrict__ beta,
                      float* __restrict__ out)
{
    const int bid = blockIdx.x;
    if (bid < NCTA1)
        lstm_fuse_body<4>(traj, tokens, habs, espeed, gconf, Wg1, bg1, Wg2, bg2,
                          W_abs, gamma, beta, out, bid * 64);
    else
        lstm_fuse_body<3>(traj, tokens, habs, espeed, gconf, Wg1, bg1, Wg2, bg2,
                          W_abs, gamma, beta, out, NCTA1*64 + (bid - NCTA1) * 48);
}

// ---------------------------------------------------------------------------
extern "C" void kernel_launch(void* const* d_in, const int* in_sizes, int n_in,
                              void* d_out, int out_size)
{
    const float* tokens = (const float*)d_in[0];
    const float* traj   = (const float*)d_in[1];
    const float* habs   = (const float*)d_in[2];
    const float* espeed = (const float*)d_in[3];
    const float* gconf  = (const float*)d_in[4];
    const float* W_ih   = (const float*)d_in[5];
    const float* W_hh   = (const float*)d_in[6];
    const float* b_ih   = (const float*)d_in[7];
    const float* b_hh   = (const float*)d_in[8];
    const float* W_rel  = (const float*)d_in[9];
    const float* W_abs  = (const float*)d_in[10];
    const float* W_g1   = (const float*)d_in[11];
    const float* b_g1   = (const float*)d_in[12];
    const float* W_g2   = (const float*)d_in[13];
    const float* b_g2   = (const float*)d_in[14];
    const float* gamma  = (const float*)d_in[15];
    const float* beta   = (const float*)d_in[16];
    float* out = (float*)d_out;

    cudaFuncSetAttribute(lstm_fuse_kernel, cudaFuncAttributeMaxDynamicSharedMemorySize, LSMEM);

    reorder_kernel<<<G4 + DIM, 128>>>(W_hh, W_ih, b_ih, b_hh, W_rel);
    lstm_fuse_kernel<<<NCTA1 + NCTA2, LTPB, LSMEM>>>(
        traj, tokens, habs, espeed, gconf, W_g1, b_g1, W_g2, b_g2,
        W_abs, gamma, beta, out);
}